// round 2
// baseline (speedup 1.0000x reference)
#include <cuda_runtime.h>
#include <math.h>
#include <stdint.h>

#define CB   16
#define CTE  128
#define CTD  128
#define CE   512
#define CH   512
#define CD   1024
#define CV   32000

// ---- scratch layout (floats) ----
#define OFF_XE   ((size_t)0)
#define SZ_XE    ((size_t)CB*CTE*CE)
#define OFF_XD   (OFF_XE + SZ_XE)
#define SZ_XD    ((size_t)CB*CTD*CE)
#define OFF_XGF  (OFF_XD + SZ_XD)
#define SZ_XGF   ((size_t)CB*CTE*4*CH)
#define OFF_XGB  (OFF_XGF + SZ_XGF)
#define SZ_XGB   ((size_t)CB*CTE*4*CH)
#define OFF_XGD  (OFF_XGB + SZ_XGB)
#define SZ_XGD   ((size_t)CB*CTD*4*CD)
#define OFF_ENC  (OFF_XGD + SZ_XGD)
#define SZ_ENC   ((size_t)CB*CTE*CD)
#define OFF_DEC  (OFF_ENC + SZ_ENC)
#define SZ_DEC   ((size_t)CB*CTD*CD)
#define OFF_Q    (OFF_DEC + SZ_DEC)
#define SZ_Q     ((size_t)CB*CTD*CD)
#define OFF_K    (OFF_Q + SZ_Q)
#define SZ_K     ((size_t)CB*CTE*CD)
#define OFF_V    (OFF_K + SZ_K)
#define SZ_V     ((size_t)CB*CTE*CD)
#define OFF_CTX  (OFF_V + SZ_V)
#define SZ_CTX   ((size_t)CB*CTD*CD)
#define OFF_LN   (OFF_CTX + SZ_CTX)
#define SZ_LN    ((size_t)CB*CTD*CD)
#define OFF_HE   (OFF_LN + SZ_LN)
#define SZ_HE    ((size_t)2*2*CH*CB)
#define OFF_HD   (OFF_HE + SZ_HE)
#define SZ_HD    ((size_t)2*CD*CB)
#define OFF_CDI  (OFF_HD + SZ_HD)
#define SZ_CDI   ((size_t)CD*CB)
#define SCRATCH_TOTAL (OFF_CDI + SZ_CDI)

__device__ float g_scratch[SCRATCH_TOTAL];
__device__ unsigned g_bar_arrive;
__device__ unsigned g_bar_release;

__device__ __forceinline__ void grid_sync_dev(unsigned nb) {
    __syncthreads();
    if (threadIdx.x == 0) {
        __threadfence();
        volatile unsigned* rel = &g_bar_release;
        unsigned gen = *rel;
        if (atomicAdd(&g_bar_arrive, 1u) == nb - 1u) {
            atomicExch(&g_bar_arrive, 0u);
            __threadfence();
            atomicAdd(&g_bar_release, 1u);
        } else {
            while (*rel == gen) { __nanosleep(64); }
            __threadfence();
        }
    }
    __syncthreads();
}

__device__ __forceinline__ float sigmoidf_(float x) { return 1.0f / (1.0f + expf(-x)); }

// ---- embedding gather ----
__global__ void __launch_bounds__(128) embed_kernel(
    const int* __restrict__ eseq, const int* __restrict__ dseq,
    const float* __restrict__ eemb, const float* __restrict__ demb,
    float* __restrict__ xe, float* __restrict__ xd)
{
    int r = blockIdx.x;
    if (r < CB * CTE) {
        int tok = eseq[r];
        ((float4*)(xe + (size_t)r * CE))[threadIdx.x] =
            ((const float4*)(eemb + (size_t)tok * CE))[threadIdx.x];
    } else {
        int r2 = r - CB * CTE;
        int tok = dseq[r2];
        ((float4*)(xd + (size_t)r2 * CE))[threadIdx.x] =
            ((const float4*)(demb + (size_t)tok * CE))[threadIdx.x];
    }
}

// ---- C[M,N] = A[M,K] @ W[N,K]^T + bias1 (+bias2). BM=128 BN=64 BK=32, 256 thr ----
__global__ void __launch_bounds__(256) gemm_tn_kernel(
    const float* __restrict__ A, const float* __restrict__ W,
    const float* __restrict__ bias1, const float* __restrict__ bias2,
    float* __restrict__ C, int M, int N, int K)
{
    __shared__ float As[32][128];
    __shared__ float Ws[32][64];
    const int tid = threadIdx.x;
    const int tm = tid >> 4, tn = tid & 15;
    const int m0 = blockIdx.y * 128, n0 = blockIdx.x * 64;

    float acc[8][4];
#pragma unroll
    for (int i = 0; i < 8; i++)
#pragma unroll
        for (int j = 0; j < 4; j++) acc[i][j] = 0.0f;

    for (int k0 = 0; k0 < K; k0 += 32) {
#pragma unroll
        for (int q = 0; q < 4; q++) {
            int i = tid * 4 + q;
            int r = i >> 3, kq = i & 7;
            float4 v = *(const float4*)(A + (size_t)(m0 + r) * K + (k0 + kq * 4));
            As[kq * 4 + 0][r] = v.x; As[kq * 4 + 1][r] = v.y;
            As[kq * 4 + 2][r] = v.z; As[kq * 4 + 3][r] = v.w;
        }
#pragma unroll
        for (int q = 0; q < 2; q++) {
            int i = tid * 2 + q;
            int r = i >> 3, kq = i & 7;
            float4 v = *(const float4*)(W + (size_t)(n0 + r) * K + (k0 + kq * 4));
            Ws[kq * 4 + 0][r] = v.x; Ws[kq * 4 + 1][r] = v.y;
            Ws[kq * 4 + 2][r] = v.z; Ws[kq * 4 + 3][r] = v.w;
        }
        __syncthreads();
#pragma unroll
        for (int kk = 0; kk < 32; kk++) {
            float a[8], bb[4];
            *(float4*)&a[0] = *(const float4*)&As[kk][tm * 8];
            *(float4*)&a[4] = *(const float4*)&As[kk][tm * 8 + 4];
            *(float4*)&bb[0] = *(const float4*)&Ws[kk][tn * 4];
#pragma unroll
            for (int i = 0; i < 8; i++)
#pragma unroll
                for (int j = 0; j < 4; j++)
                    acc[i][j] = fmaf(a[i], bb[j], acc[i][j]);
        }
        __syncthreads();
    }

    float bb[4];
#pragma unroll
    for (int j = 0; j < 4; j++) {
        int n = n0 + tn * 4 + j;
        float t = bias1 ? bias1[n] : 0.0f;
        if (bias2) t += bias2[n];
        bb[j] = t;
    }
#pragma unroll
    for (int i = 0; i < 8; i++) {
        int m = m0 + tm * 8 + i;
        float4 o;
        o.x = acc[i][0] + bb[0]; o.y = acc[i][1] + bb[1];
        o.z = acc[i][2] + bb[2]; o.w = acc[i][3] + bb[3];
        *(float4*)(C + (size_t)m * N + n0 + tn * 4) = o;
    }
}

// ---- bidirectional encoder recurrence: 128 CTAs (0-63 fwd, 64-127 bwd) ----
__global__ void __launch_bounds__(128) enc_rnn_kernel(
    const float* __restrict__ Whh_f, const float* __restrict__ Whh_b,
    const float* __restrict__ xgf, const float* __restrict__ xgb,
    float* __restrict__ enc, float* __restrict__ hebuf,
    float* __restrict__ hd0, float* __restrict__ cdi)
{
    __shared__ float sh[CH * CB];
    const int tid = threadIdx.x;
    const int b = tid & 15, ul = tid >> 4;
    const int dir = blockIdx.x >> 6;
    const int u = (blockIdx.x & 63) * 8 + ul;

    const float* Whh = dir ? Whh_b : Whh_f;
    const float* xg  = dir ? xgb : xgf;
    const float4* w0 = (const float4*)(Whh + (size_t)u * CH);
    const float4* w1 = (const float4*)(Whh + (size_t)(CH + u) * CH);
    const float4* w2 = (const float4*)(Whh + (size_t)(2 * CH + u) * CH);
    const float4* w3 = (const float4*)(Whh + (size_t)(3 * CH + u) * CH);

    float c = 0.0f, h = 0.0f;
    hebuf[(size_t)(0 * 2 + dir) * (CH * CB) + u * CB + b] = 0.0f;
    grid_sync_dev(gridDim.x);

    for (int t = 0; t < CTE; t++) {
        const int cur = t & 1;
        {
            const float4* src = (const float4*)(hebuf + (size_t)(cur * 2 + dir) * (CH * CB));
            float4* dst = (float4*)sh;
#pragma unroll
            for (int i = 0; i < (CH * CB / 4) / 128; i++)
                dst[tid + i * 128] = src[tid + i * 128];
        }
        __syncthreads();

        const int te = dir ? (CTE - 1 - t) : t;
        size_t xb = ((size_t)(b * CTE + te)) * (4 * CH) + u;
        float a0 = xg[xb], a1 = xg[xb + CH], a2 = xg[xb + 2 * CH], a3 = xg[xb + 3 * CH];

#pragma unroll 4
        for (int k4 = 0; k4 < CH / 4; k4++) {
            float4 wi = w0[k4], wf = w1[k4], wg = w2[k4], wo = w3[k4];
            const float* hp = sh + (k4 * 4) * CB + b;
            float h0 = hp[0], h1 = hp[CB], h2 = hp[2 * CB], h3 = hp[3 * CB];
            a0 = fmaf(wi.x,h0,a0); a0 = fmaf(wi.y,h1,a0); a0 = fmaf(wi.z,h2,a0); a0 = fmaf(wi.w,h3,a0);
            a1 = fmaf(wf.x,h0,a1); a1 = fmaf(wf.y,h1,a1); a1 = fmaf(wf.z,h2,a1); a1 = fmaf(wf.w,h3,a1);
            a2 = fmaf(wg.x,h0,a2); a2 = fmaf(wg.y,h1,a2); a2 = fmaf(wg.z,h2,a2); a2 = fmaf(wg.w,h3,a2);
            a3 = fmaf(wo.x,h0,a3); a3 = fmaf(wo.y,h1,a3); a3 = fmaf(wo.z,h2,a3); a3 = fmaf(wo.w,h3,a3);
        }

        float ig = sigmoidf_(a0), fg = sigmoidf_(a1);
        float gg = tanhf(a2),     og = sigmoidf_(a3);
        c = fg * c + ig * gg;
        h = og * tanhf(c);

        hebuf[(size_t)((cur ^ 1) * 2 + dir) * (CH * CB) + u * CB + b] = h;
        enc[((size_t)(b * CTE + te)) * CD + dir * CH + u] = h;
        grid_sync_dev(gridDim.x);
    }

    hd0[(size_t)(dir * CH + u) * CB + b] = h;
    cdi[(size_t)(dir * CH + u) * CB + b] = c;
}

// ---- decoder recurrence: 128 CTAs, 64KB dynamic smem ----
__global__ void __launch_bounds__(128) dec_rnn_kernel(
    const float* __restrict__ Whh, const float* __restrict__ xg,
    float* __restrict__ dec, float* __restrict__ hbuf,
    const float* __restrict__ cinit)
{
    extern __shared__ float sh[];
    const int tid = threadIdx.x;
    const int b = tid & 15, ul = tid >> 4;
    const int u = blockIdx.x * 8 + ul;

    const float4* w0 = (const float4*)(Whh + (size_t)u * CD);
    const float4* w1 = (const float4*)(Whh + (size_t)(CD + u) * CD);
    const float4* w2 = (const float4*)(Whh + (size_t)(2 * CD + u) * CD);
    const float4* w3 = (const float4*)(Whh + (size_t)(3 * CD + u) * CD);

    float c = cinit[(size_t)u * CB + b];

    for (int t = 0; t < CTD; t++) {
        const int cur = t & 1;
        {
            const float4* src = (const float4*)(hbuf + (size_t)cur * (CD * CB));
            float4* dst = (float4*)sh;
#pragma unroll
            for (int i = 0; i < (CD * CB / 4) / 128; i++)
                dst[tid + i * 128] = src[tid + i * 128];
        }
        __syncthreads();

        size_t xb = ((size_t)(b * CTD + t)) * (4 * CD) + u;
        float a0 = xg[xb], a1 = xg[xb + CD], a2 = xg[xb + 2 * CD], a3 = xg[xb + 3 * CD];

#pragma unroll 2
        for (int k4 = 0; k4 < CD / 4; k4++) {
            float4 wi = w0[k4], wf = w1[k4], wg = w2[k4], wo = w3[k4];
            const float* hp = sh + (k4 * 4) * CB + b;
            float h0 = hp[0], h1 = hp[CB], h2 = hp[2 * CB], h3 = hp[3 * CB];
            a0 = fmaf(wi.x,h0,a0); a0 = fmaf(wi.y,h1,a0); a0 = fmaf(wi.z,h2,a0); a0 = fmaf(wi.w,h3,a0);
            a1 = fmaf(wf.x,h0,a1); a1 = fmaf(wf.y,h1,a1); a1 = fmaf(wf.z,h2,a1); a1 = fmaf(wf.w,h3,a1);
            a2 = fmaf(wg.x,h0,a2); a2 = fmaf(wg.y,h1,a2); a2 = fmaf(wg.z,h2,a2); a2 = fmaf(wg.w,h3,a2);
            a3 = fmaf(wo.x,h0,a3); a3 = fmaf(wo.y,h1,a3); a3 = fmaf(wo.z,h2,a3); a3 = fmaf(wo.w,h3,a3);
        }

        float ig = sigmoidf_(a0), fg = sigmoidf_(a1);
        float gg = tanhf(a2),     og = sigmoidf_(a3);
        c = fg * c + ig * gg;
        float h = og * tanhf(c);

        hbuf[(size_t)(cur ^ 1) * (CD * CB) + (size_t)u * CB + b] = h;
        dec[((size_t)(b * CTD + t)) * CD + u] = h;
        grid_sync_dev(gridDim.x);
    }
}

// ---- fused attention: one block per (b, qt) ----
__global__ void __launch_bounds__(128) attn_kernel(
    const int* __restrict__ eseq,
    const float* __restrict__ q, const float* __restrict__ k,
    const float* __restrict__ v, float* __restrict__ ctx)
{
    __shared__ float qs[CD];
    __shared__ float att[CTE];
    __shared__ float red[128];
    const int tid = threadIdx.x;
    const int b = blockIdx.x >> 7, qt = blockIdx.x & 127;
    const size_t qrow = (size_t)(b * CTD + qt) * CD;

    ((float4*)qs)[tid]       = ((const float4*)(q + qrow))[tid];
    ((float4*)qs)[tid + 128] = ((const float4*)(q + qrow))[tid + 128];
    __syncthreads();

    const float4* kr = (const float4*)(k + (size_t)(b * CTE + tid) * CD);
    float s = 0.0f;
#pragma unroll 8
    for (int k4 = 0; k4 < CD / 4; k4++) {
        float4 kv = kr[k4];
        s = fmaf(qs[k4*4+0], kv.x, s); s = fmaf(qs[k4*4+1], kv.y, s);
        s = fmaf(qs[k4*4+2], kv.z, s); s = fmaf(qs[k4*4+3], kv.w, s);
    }
    s *= 0.03125f;
    if (eseq[b * CTE + tid] == 0) s = -1e30f;

    red[tid] = s; __syncthreads();
#pragma unroll
    for (int o = 64; o > 0; o >>= 1) {
        if (tid < o) red[tid] = fmaxf(red[tid], red[tid + o]);
        __syncthreads();
    }
    float mx = red[0]; __syncthreads();
    float e = expf(s - mx);
    red[tid] = e; __syncthreads();
#pragma unroll
    for (int o = 64; o > 0; o >>= 1) {
        if (tid < o) red[tid] += red[tid + o];
        __syncthreads();
    }
    att[tid] = e / red[0];
    __syncthreads();

    float acc[8] = {0,0,0,0,0,0,0,0};
    for (int kt = 0; kt < CTE; kt++) {
        float a = att[kt];
        const float* vr = v + (size_t)(b * CTE + kt) * CD;
#pragma unroll
        for (int j = 0; j < 8; j++) acc[j] = fmaf(a, vr[tid + j * 128], acc[j]);
    }
    float* cr = ctx + (size_t)(b * CTD + qt) * CD;
#pragma unroll
    for (int j = 0; j < 8; j++) cr[tid + j * 128] = acc[j];
}

// ---- tanh(dec + ctx) -> layernorm ----
__global__ void __launch_bounds__(256) tanh_ln_kernel(
    const float* __restrict__ dec, const float* __restrict__ ctx,
    const float* __restrict__ gamma, const float* __restrict__ beta,
    float* __restrict__ ln)
{
    __shared__ float rs[8], rss[8];
    const int tid = threadIdx.x;
    const int row = blockIdx.x;
    const float4 a = ((const float4*)(dec + (size_t)row * CD))[tid];
    const float4 b = ((const float4*)(ctx + (size_t)row * CD))[tid];
    float t0 = tanhf(a.x + b.x), t1 = tanhf(a.y + b.y);
    float t2 = tanhf(a.z + b.z), t3 = tanhf(a.w + b.w);
    float s = t0 + t1 + t2 + t3;
    float ss = t0*t0 + t1*t1 + t2*t2 + t3*t3;
#pragma unroll
    for (int o = 16; o > 0; o >>= 1) {
        s  += __shfl_xor_sync(0xffffffffu, s, o);
        ss += __shfl_xor_sync(0xffffffffu, ss, o);
    }
    if ((tid & 31) == 0) { rs[tid >> 5] = s; rss[tid >> 5] = ss; }
    __syncthreads();
    if (tid < 8) { s = rs[tid]; ss = rss[tid]; }
    else { s = 0; ss = 0; }
    if (tid < 32) {
#pragma unroll
        for (int o = 4; o > 0; o >>= 1) {
            s  += __shfl_xor_sync(0xffffffffu, s, o);
            ss += __shfl_xor_sync(0xffffffffu, ss, o);
        }
        if (tid == 0) { rs[0] = s; rss[0] = ss; }
    }
    __syncthreads();
    float mu = rs[0] * (1.0f / CD);
    float var = rss[0] * (1.0f / CD) - mu * mu;
    float rstd = rsqrtf(var + 1e-5f);
    const float4 g = ((const float4*)gamma)[tid];
    const float4 be = ((const float4*)beta)[tid];
    float4 o;
    o.x = (t0 - mu) * rstd * g.x + be.x;
    o.y = (t1 - mu) * rstd * g.y + be.y;
    o.z = (t2 - mu) * rstd * g.z + be.z;
    o.w = (t3 - mu) * rstd * g.w + be.w;
    ((float4*)(ln + (size_t)row * CD))[tid] = o;
}

extern "C" void kernel_launch(void* const* d_in, const int* in_sizes, int n_in,
                              void* d_out, int out_size) {
    const int*   eseq  = (const int*)d_in[0];
    const int*   dseq  = (const int*)d_in[1];
    const float* eemb  = (const float*)d_in[2];
    const float* demb  = (const float*)d_in[3];
    const float* Wih_f = (const float*)d_in[4];
    const float* Whh_f = (const float*)d_in[5];
    const float* bih_f = (const float*)d_in[6];
    const float* bhh_f = (const float*)d_in[7];
    const float* Wih_b = (const float*)d_in[8];
    const float* Whh_b = (const float*)d_in[9];
    const float* bih_b = (const float*)d_in[10];
    const float* bhh_b = (const float*)d_in[11];
    const float* Wih_d = (const float*)d_in[12];
    const float* Whh_d = (const float*)d_in[13];
    const float* bih_d = (const float*)d_in[14];
    const float* bhh_d = (const float*)d_in[15];
    const float* Wq = (const float*)d_in[16];
    const float* bq = (const float*)d_in[17];
    const float* Wk = (const float*)d_in[18];
    const float* bk = (const float*)d_in[19];
    const float* Wv = (const float*)d_in[20];
    const float* bv = (const float*)d_in[21];
    const float* Wfc = (const float*)d_in[22];
    const float* bfc = (const float*)d_in[23];
    const float* gamma = (const float*)d_in[24];
    const float* beta  = (const float*)d_in[25];
    float* out = (float*)d_out;

    float* S = nullptr;
    cudaGetSymbolAddress((void**)&S, g_scratch);
    float* xe  = S + OFF_XE;
    float* xd  = S + OFF_XD;
    float* xgf = S + OFF_XGF;
    float* xgb = S + OFF_XGB;
    float* xgd = S + OFF_XGD;
    float* enc = S + OFF_ENC;
    float* dec = S + OFF_DEC;
    float* q   = S + OFF_Q;
    float* k   = S + OFF_K;
    float* v   = S + OFF_V;
    float* ctx = S + OFF_CTX;
    float* ln  = S + OFF_LN;
    float* heb = S + OFF_HE;
    float* hdb = S + OFF_HD;
    float* cdi = S + OFF_CDI;

    static bool attr_set = false;
    if (!attr_set) {
        cudaFuncSetAttribute(dec_rnn_kernel,
                             cudaFuncAttributeMaxDynamicSharedMemorySize, CD * CB * 4);
        attr_set = true;
    }

    const int M = CB * CTE;  // 2048 (== CB*CTD)

    embed_kernel<<<CB * CTE + CB * CTD, 128>>>(eseq, dseq, eemb, demb, xe, xd);

    // input-gate GEMMs: xg = x @ Wih^T + bih + bhh
    gemm_tn_kernel<<<dim3(4*CH/64, M/128), 256>>>(xe, Wih_f, bih_f, bhh_f, xgf, M, 4*CH, CE);
    gemm_tn_kernel<<<dim3(4*CH/64, M/128), 256>>>(xe, Wih_b, bih_b, bhh_b, xgb, M, 4*CH, CE);
    gemm_tn_kernel<<<dim3(4*CD/64, M/128), 256>>>(xd, Wih_d, bih_d, bhh_d, xgd, M, 4*CD, CE);

    enc_rnn_kernel<<<128, 128>>>(Whh_f, Whh_b, xgf, xgb, enc, heb, hdb, cdi);
    dec_rnn_kernel<<<128, 128, CD * CB * 4>>>(Whh_d, xgd, dec, hdb, cdi);

    gemm_tn_kernel<<<dim3(CD/64, M/128), 256>>>(dec, Wq, bq, nullptr, q, M, CD, CD);
    gemm_tn_kernel<<<dim3(CD/64, M/128), 256>>>(enc, Wk, bk, nullptr, k, M, CD, CD);
    gemm_tn_kernel<<<dim3(CD/64, M/128), 256>>>(enc, Wv, bv, nullptr, v, M, CD, CD);

    attn_kernel<<<CB * CTD, 128>>>(eseq, q, k, v, ctx);
    tanh_ln_kernel<<<CB * CTD, 256>>>(dec, ctx, gamma, beta, ln);

    gemm_tn_kernel<<<dim3(CV/64, M/128), 256>>>(ln, Wfc, bfc, nullptr, out, M, CV, CD);
}

// round 4
// speedup vs baseline: 1.2758x; 1.2758x over previous
#include <cuda_runtime.h>
#include <math.h>
#include <stdint.h>

#define CB   16
#define CTE  128
#define CTD  128
#define CE   512
#define CH   512
#define CD   1024
#define CV   32000

// ---- scratch layout (floats) ----
#define OFF_XE   ((size_t)0)
#define SZ_XE    ((size_t)CB*CTE*CE)
#define OFF_XD   (OFF_XE + SZ_XE)
#define SZ_XD    ((size_t)CB*CTD*CE)
#define OFF_XGF  (OFF_XD + SZ_XD)
#define SZ_XGF   ((size_t)CB*CTE*4*CH)
#define OFF_XGB  (OFF_XGF + SZ_XGF)
#define SZ_XGB   ((size_t)CB*CTE*4*CH)
#define OFF_XGD  (OFF_XGB + SZ_XGB)
#define SZ_XGD   ((size_t)CB*CTD*4*CD)
#define OFF_ENC  (OFF_XGD + SZ_XGD)
#define SZ_ENC   ((size_t)CB*CTE*CD)
#define OFF_DEC  (OFF_ENC + SZ_ENC)
#define SZ_DEC   ((size_t)CB*CTD*CD)
#define OFF_Q    (OFF_DEC + SZ_DEC)
#define SZ_Q     ((size_t)CB*CTD*CD)
#define OFF_K    (OFF_Q + SZ_Q)
#define SZ_K     ((size_t)CB*CTE*CD)
#define OFF_V    (OFF_K + SZ_K)
#define SZ_V     ((size_t)CB*CTE*CD)
#define OFF_CTX  (OFF_V + SZ_V)
#define SZ_CTX   ((size_t)CB*CTD*CD)
#define OFF_LN   (OFF_CTX + SZ_CTX)
#define SZ_LN    ((size_t)CB*CTD*CD)
#define OFF_HE   (OFF_LN + SZ_LN)
#define SZ_HE    ((size_t)2*2*CH*CB)
#define OFF_HD   (OFF_HE + SZ_HE)
#define SZ_HD    ((size_t)2*CD*CB)
#define OFF_CDI  (OFF_HD + SZ_HD)
#define SZ_CDI   ((size_t)CD*CB)
#define SCRATCH_TOTAL (OFF_CDI + SZ_CDI)

__device__ float g_scratch[SCRATCH_TOTAL];
__device__ unsigned g_bar_arrive;
__device__ unsigned g_bar_release;

__device__ __forceinline__ void grid_sync_dev(unsigned nb) {
    __syncthreads();
    if (threadIdx.x == 0) {
        __threadfence();
        volatile unsigned* rel = &g_bar_release;
        unsigned gen = *rel;
        if (atomicAdd(&g_bar_arrive, 1u) == nb - 1u) {
            atomicExch(&g_bar_arrive, 0u);
            __threadfence();
            atomicAdd(&g_bar_release, 1u);
        } else {
            while (*rel == gen) { __nanosleep(64); }
            __threadfence();
        }
    }
    __syncthreads();
}

__device__ __forceinline__ float sigmoidf_(float x) { return 1.0f / (1.0f + expf(-x)); }

__device__ __forceinline__ uint32_t smem_u32(const void* p) {
    uint32_t a;
    asm("{ .reg .u64 t; cvta.to.shared.u64 t, %1; cvt.u32.u64 %0, t; }" : "=r"(a) : "l"(p));
    return a;
}
__device__ __forceinline__ void cp_async16(uint32_t dst, const void* src) {
    asm volatile("cp.async.cg.shared.global [%0], [%1], 16;" :: "r"(dst), "l"(src));
}
__device__ __forceinline__ void cp_commit() { asm volatile("cp.async.commit_group;" ::: "memory"); }
__device__ __forceinline__ uint32_t f2tf32(float f) {
    uint32_t u;
    asm("cvt.rna.tf32.f32 %0, %1;" : "=r"(u) : "f"(f));
    return u;
}
__device__ __forceinline__ void mma_tf32(float* c, const uint32_t* a, const uint32_t* b) {
    asm volatile(
        "mma.sync.aligned.m16n8k8.row.col.f32.tf32.tf32.f32 "
        "{%0,%1,%2,%3}, {%4,%5,%6,%7}, {%8,%9}, {%0,%1,%2,%3};"
        : "+f"(c[0]), "+f"(c[1]), "+f"(c[2]), "+f"(c[3])
        : "r"(a[0]), "r"(a[1]), "r"(a[2]), "r"(a[3]), "r"(b[0]), "r"(b[1]));
}

// ===================== tf32 mma.sync GEMM =====================
// C[M,N] = A[M,K] @ W[N,K]^T + bias1[n] (+bias2[n])
// BM=128, BN=128, BK=32, 256 threads = 8 warps (2m x 4n), warp tile 64x32.
// Smem rows padded to 36 floats -> conflict-free fragment loads.
#define BM 128
#define BN 128
#define GBK 32
#define GST 3
#define PADK 36
#define TILE_F (128 * PADK)
#define GEMM_SMEM (GST * 2 * TILE_F * 4)

__global__ void __launch_bounds__(256) gemm_tc_kernel(
    const float* __restrict__ A, const float* __restrict__ W,
    const float* __restrict__ bias1, const float* __restrict__ bias2,
    float* __restrict__ C, int N, int K)
{
    extern __shared__ float dsm[];
    float* sA = dsm;                       // [GST][128][PADK]
    float* sB = dsm + GST * TILE_F;        // [GST][128][PADK]

    const int tid  = threadIdx.x;
    const int warp = tid >> 5;
    const int lane = tid & 31;
    const int g    = lane >> 2;            // group id 0..7
    const int tig  = lane & 3;             // thread in group
    const int wm   = warp >> 2;            // 0..1
    const int wn   = warp & 3;             // 0..3
    const int m0   = blockIdx.x * BM;      // m on x -> m-blocks sharing W run together
    const int n0   = blockIdx.y * BN;
    const int nst  = K / GBK;

    const uint32_t sA_u = smem_u32(sA);
    const uint32_t sB_u = smem_u32(sB);

    float acc[4][4][4];
#pragma unroll
    for (int i = 0; i < 4; i++)
#pragma unroll
        for (int j = 0; j < 4; j++)
#pragma unroll
            for (int r = 0; r < 4; r++) acc[i][j][r] = 0.0f;

    auto load_stage = [&](int kidx, int s) {
        const float* Ag = A + (size_t)m0 * K + kidx * GBK;
        const float* Wg = W + (size_t)n0 * K + kidx * GBK;
        uint32_t aBase = sA_u + (uint32_t)(s * TILE_F * 4);
        uint32_t bBase = sB_u + (uint32_t)(s * TILE_F * 4);
#pragma unroll
        for (int q = 0; q < 4; q++) {
            int ch = q * 256 + tid;        // 1024 chunks of 16B
            int r = ch >> 3, c = ch & 7;
            cp_async16(aBase + (uint32_t)((r * PADK + c * 4) * 4),
                       Ag + (size_t)r * K + c * 4);
        }
#pragma unroll
        for (int q = 0; q < 4; q++) {
            int ch = q * 256 + tid;
            int r = ch >> 3, c = ch & 7;
            cp_async16(bBase + (uint32_t)((r * PADK + c * 4) * 4),
                       Wg + (size_t)r * K + c * 4);
        }
        cp_commit();
    };

    load_stage(0, 0);
    load_stage(1, 1);

    for (int i = 0; i < nst; i++) {
        if (i + 2 < nst) {
            load_stage(i + 2, (i + 2) % GST);
            asm volatile("cp.async.wait_group 2;" ::: "memory");
        } else if (i + 1 < nst) {
            asm volatile("cp.async.wait_group 1;" ::: "memory");
        } else {
            asm volatile("cp.async.wait_group 0;" ::: "memory");
        }
        __syncthreads();

        const int s = i % GST;
        const float* aS = sA + s * TILE_F;
        const float* bS = sB + s * TILE_F;

#pragma unroll
        for (int ks = 0; ks < 4; ks++) {
            const int kc = ks * 8 + tig;
            uint32_t af[4][4], bf[4][2];
#pragma unroll
            for (int mt = 0; mt < 4; mt++) {
                int row = wm * 64 + mt * 16 + g;
                af[mt][0] = f2tf32(aS[row * PADK + kc]);
                af[mt][1] = f2tf32(aS[(row + 8) * PADK + kc]);
                af[mt][2] = f2tf32(aS[row * PADK + kc + 4]);
                af[mt][3] = f2tf32(aS[(row + 8) * PADK + kc + 4]);
            }
#pragma unroll
            for (int nt = 0; nt < 4; nt++) {
                int n = wn * 32 + nt * 8 + g;
                bf[nt][0] = f2tf32(bS[n * PADK + kc]);
                bf[nt][1] = f2tf32(bS[n * PADK + kc + 4]);
            }
#pragma unroll
            for (int mt = 0; mt < 4; mt++)
#pragma unroll
                for (int nt = 0; nt < 4; nt++)
                    mma_tf32(acc[mt][nt], af[mt], bf[nt]);
        }
        __syncthreads();
    }

    // epilogue
#pragma unroll
    for (int nt = 0; nt < 4; nt++) {
        int cn = n0 + wn * 32 + nt * 8 + 2 * tig;
        float b0 = bias1 ? bias1[cn] : 0.0f;
        float b1 = bias1 ? bias1[cn + 1] : 0.0f;
        if (bias2) { b0 += bias2[cn]; b1 += bias2[cn + 1]; }
#pragma unroll
        for (int mt = 0; mt < 4; mt++) {
            int r = m0 + wm * 64 + mt * 16 + g;
            float2 o0 = make_float2(acc[mt][nt][0] + b0, acc[mt][nt][1] + b1);
            float2 o1 = make_float2(acc[mt][nt][2] + b0, acc[mt][nt][3] + b1);
            *(float2*)(C + (size_t)r * N + cn) = o0;
            *(float2*)(C + (size_t)(r + 8) * N + cn) = o1;
        }
    }
}

// ---- embedding gather ----
__global__ void __launch_bounds__(128) embed_kernel(
    const int* __restrict__ eseq, const int* __restrict__ dseq,
    const float* __restrict__ eemb, const float* __restrict__ demb,
    float* __restrict__ xe, float* __restrict__ xd)
{
    int r = blockIdx.x;
    if (r < CB * CTE) {
        int tok = eseq[r];
        ((float4*)(xe + (size_t)r * CE))[threadIdx.x] =
            ((const float4*)(eemb + (size_t)tok * CE))[threadIdx.x];
    } else {
        int r2 = r - CB * CTE;
        int tok = dseq[r2];
        ((float4*)(xd + (size_t)r2 * CE))[threadIdx.x] =
            ((const float4*)(demb + (size_t)tok * CE))[threadIdx.x];
    }
}

// ---- bidirectional encoder recurrence: 128 CTAs (0-63 fwd, 64-127 bwd) ----
__global__ void __launch_bounds__(128) enc_rnn_kernel(
    const float* __restrict__ Whh_f, const float* __restrict__ Whh_b,
    const float* __restrict__ xgf, const float* __restrict__ xgb,
    float* __restrict__ enc, float* __restrict__ hebuf,
    float* __restrict__ hd0, float* __restrict__ cdi)
{
    __shared__ float sh[CH * CB];
    const int tid = threadIdx.x;
    const int b = tid & 15, ul = tid >> 4;
    const int dir = blockIdx.x >> 6;
    const int u = (blockIdx.x & 63) * 8 + ul;

    const float* Whh = dir ? Whh_b : Whh_f;
    const float* xg  = dir ? xgb : xgf;
    const float4* w0 = (const float4*)(Whh + (size_t)u * CH);
    const float4* w1 = (const float4*)(Whh + (size_t)(CH + u) * CH);
    const float4* w2 = (const float4*)(Whh + (size_t)(2 * CH + u) * CH);
    const float4* w3 = (const float4*)(Whh + (size_t)(3 * CH + u) * CH);

    float c = 0.0f, h = 0.0f;
    hebuf[(size_t)(0 * 2 + dir) * (CH * CB) + u * CB + b] = 0.0f;
    grid_sync_dev(gridDim.x);

    for (int t = 0; t < CTE; t++) {
        const int cur = t & 1;
        {
            const float4* src = (const float4*)(hebuf + (size_t)(cur * 2 + dir) * (CH * CB));
            float4* dst = (float4*)sh;
#pragma unroll
            for (int i = 0; i < (CH * CB / 4) / 128; i++)
                dst[tid + i * 128] = src[tid + i * 128];
        }
        __syncthreads();

        const int te = dir ? (CTE - 1 - t) : t;
        size_t xb = ((size_t)(b * CTE + te)) * (4 * CH) + u;
        float a0 = xg[xb], a1 = xg[xb + CH], a2 = xg[xb + 2 * CH], a3 = xg[xb + 3 * CH];

#pragma unroll 4
        for (int k4 = 0; k4 < CH / 4; k4++) {
            float4 wi = w0[k4], wf = w1[k4], wg = w2[k4], wo = w3[k4];
            const float* hp = sh + (k4 * 4) * CB + b;
            float h0 = hp[0], h1 = hp[CB], h2 = hp[2 * CB], h3 = hp[3 * CB];
            a0 = fmaf(wi.x,h0,a0); a0 = fmaf(wi.y,h1,a0); a0 = fmaf(wi.z,h2,a0); a0 = fmaf(wi.w,h3,a0);
            a1 = fmaf(wf.x,h0,a1); a1 = fmaf(wf.y,h1,a1); a1 = fmaf(wf.z,h2,a1); a1 = fmaf(wf.w,h3,a1);
            a2 = fmaf(wg.x,h0,a2); a2 = fmaf(wg.y,h1,a2); a2 = fmaf(wg.z,h2,a2); a2 = fmaf(wg.w,h3,a2);
            a3 = fmaf(wo.x,h0,a3); a3 = fmaf(wo.y,h1,a3); a3 = fmaf(wo.z,h2,a3); a3 = fmaf(wo.w,h3,a3);
        }

        float ig = sigmoidf_(a0), fg = sigmoidf_(a1);
        float gg = tanhf(a2),     og = sigmoidf_(a3);
        c = fg * c + ig * gg;
        h = og * tanhf(c);

        hebuf[(size_t)((cur ^ 1) * 2 + dir) * (CH * CB) + u * CB + b] = h;
        enc[((size_t)(b * CTE + te)) * CD + dir * CH + u] = h;
        grid_sync_dev(gridDim.x);
    }

    hd0[(size_t)(dir * CH + u) * CB + b] = h;
    cdi[(size_t)(dir * CH + u) * CB + b] = c;
}

// ---- decoder recurrence: 128 CTAs, 64KB dynamic smem ----
__global__ void __launch_bounds__(128) dec_rnn_kernel(
    const float* __restrict__ Whh, const float* __restrict__ xg,
    float* __restrict__ dec, float* __restrict__ hbuf,
    const float* __restrict__ cinit)
{
    extern __shared__ float sh[];
    const int tid = threadIdx.x;
    const int b = tid & 15, ul = tid >> 4;
    const int u = blockIdx.x * 8 + ul;

    const float4* w0 = (const float4*)(Whh + (size_t)u * CD);
    const float4* w1 = (const float4*)(Whh + (size_t)(CD + u) * CD);
    const float4* w2 = (const float4*)(Whh + (size_t)(2 * CD + u) * CD);
    const float4* w3 = (const float4*)(Whh + (size_t)(3 * CD + u) * CD);

    float c = cinit[(size_t)u * CB + b];

    for (int t = 0; t < CTD; t++) {
        const int cur = t & 1;
        {
            const float4* src = (const float4*)(hbuf + (size_t)cur * (CD * CB));
            float4* dst = (float4*)sh;
#pragma unroll
            for (int i = 0; i < (CD * CB / 4) / 128; i++)
                dst[tid + i * 128] = src[tid + i * 128];
        }
        __syncthreads();

        size_t xb = ((size_t)(b * CTD + t)) * (4 * CD) + u;
        float a0 = xg[xb], a1 = xg[xb + CD], a2 = xg[xb + 2 * CD], a3 = xg[xb + 3 * CD];

#pragma unroll 2
        for (int k4 = 0; k4 < CD / 4; k4++) {
            float4 wi = w0[k4], wf = w1[k4], wg = w2[k4], wo = w3[k4];
            const float* hp = sh + (k4 * 4) * CB + b;
            float h0 = hp[0], h1 = hp[CB], h2 = hp[2 * CB], h3 = hp[3 * CB];
            a0 = fmaf(wi.x,h0,a0); a0 = fmaf(wi.y,h1,a0); a0 = fmaf(wi.z,h2,a0); a0 = fmaf(wi.w,h3,a0);
            a1 = fmaf(wf.x,h0,a1); a1 = fmaf(wf.y,h1,a1); a1 = fmaf(wf.z,h2,a1); a1 = fmaf(wf.w,h3,a1);
            a2 = fmaf(wg.x,h0,a2); a2 = fmaf(wg.y,h1,a2); a2 = fmaf(wg.z,h2,a2); a2 = fmaf(wg.w,h3,a2);
            a3 = fmaf(wo.x,h0,a3); a3 = fmaf(wo.y,h1,a3); a3 = fmaf(wo.z,h2,a3); a3 = fmaf(wo.w,h3,a3);
        }

        float ig = sigmoidf_(a0), fg = sigmoidf_(a1);
        float gg = tanhf(a2),     og = sigmoidf_(a3);
        c = fg * c + ig * gg;
        float h = og * tanhf(c);

        hbuf[(size_t)(cur ^ 1) * (CD * CB) + (size_t)u * CB + b] = h;
        dec[((size_t)(b * CTD + t)) * CD + u] = h;
        grid_sync_dev(gridDim.x);
    }
}

// ---- fused attention: one block per (b, qt) ----
__global__ void __launch_bounds__(128) attn_kernel(
    const int* __restrict__ eseq,
    const float* __restrict__ q, const float* __restrict__ k,
    const float* __restrict__ v, float* __restrict__ ctx)
{
    __shared__ float qs[CD];
    __shared__ float att[CTE];
    __shared__ float red[128];
    const int tid = threadIdx.x;
    const int b = blockIdx.x >> 7, qt = blockIdx.x & 127;
    const size_t qrow = (size_t)(b * CTD + qt) * CD;

    ((float4*)qs)[tid]       = ((const float4*)(q + qrow))[tid];
    ((float4*)qs)[tid + 128] = ((const float4*)(q + qrow))[tid + 128];
    __syncthreads();

    const float4* kr = (const float4*)(k + (size_t)(b * CTE + tid) * CD);
    float s = 0.0f;
#pragma unroll 8
    for (int k4 = 0; k4 < CD / 4; k4++) {
        float4 kv = kr[k4];
        s = fmaf(qs[k4*4+0], kv.x, s); s = fmaf(qs[k4*4+1], kv.y, s);
        s = fmaf(qs[k4*4+2], kv.z, s); s = fmaf(qs[k4*4+3], kv.w, s);
    }
    s *= 0.03125f;
    if (eseq[b * CTE + tid] == 0) s = -1e30f;

    red[tid] = s; __syncthreads();
#pragma unroll
    for (int o = 64; o > 0; o >>= 1) {
        if (tid < o) red[tid] = fmaxf(red[tid], red[tid + o]);
        __syncthreads();
    }
    float mx = red[0]; __syncthreads();
    float e = expf(s - mx);
    red[tid] = e; __syncthreads();
#pragma unroll
    for (int o = 64; o > 0; o >>= 1) {
        if (tid < o) red[tid] += red[tid + o];
        __syncthreads();
    }
    att[tid] = e / red[0];
    __syncthreads();

    float acc[8] = {0,0,0,0,0,0,0,0};
    for (int kt = 0; kt < CTE; kt++) {
        float a = att[kt];
        const float* vr = v + (size_t)(b * CTE + kt) * CD;
#pragma unroll
        for (int j = 0; j < 8; j++) acc[j] = fmaf(a, vr[tid + j * 128], acc[j]);
    }
    float* cr = ctx + (size_t)(b * CTD + qt) * CD;
#pragma unroll
    for (int j = 0; j < 8; j++) cr[tid + j * 128] = acc[j];
}

// ---- tanh(dec + ctx) -> layernorm ----
__global__ void __launch_bounds__(256) tanh_ln_kernel(
    const float* __restrict__ dec, const float* __restrict__ ctx,
    const float* __restrict__ gamma, const float* __restrict__ beta,
    float* __restrict__ ln)
{
    __shared__ float rs[8], rss[8];
    const int tid = threadIdx.x;
    const int row = blockIdx.x;
    const float4 a = ((const float4*)(dec + (size_t)row * CD))[tid];
    const float4 b = ((const float4*)(ctx + (size_t)row * CD))[tid];
    float t0 = tanhf(a.x + b.x), t1 = tanhf(a.y + b.y);
    float t2 = tanhf(a.z + b.z), t3 = tanhf(a.w + b.w);
    float s = t0 + t1 + t2 + t3;
    float ss = t0*t0 + t1*t1 + t2*t2 + t3*t3;
#pragma unroll
    for (int o = 16; o > 0; o >>= 1) {
        s  += __shfl_xor_sync(0xffffffffu, s, o);
        ss += __shfl_xor_sync(0xffffffffu, ss, o);
    }
    if ((tid & 31) == 0) { rs[tid >> 5] = s; rss[tid >> 5] = ss; }
    __syncthreads();
    if (tid < 8) { s = rs[tid]; ss = rss[tid]; }
    else { s = 0; ss = 0; }
    if (tid < 32) {
#pragma unroll
        for (int o = 4; o > 0; o >>= 1) {
            s  += __shfl_xor_sync(0xffffffffu, s, o);
            ss += __shfl_xor_sync(0xffffffffu, ss, o);
        }
        if (tid == 0) { rs[0] = s; rss[0] = ss; }
    }
    __syncthreads();
    float mu = rs[0] * (1.0f / CD);
    float var = rss[0] * (1.0f / CD) - mu * mu;
    float rstd = rsqrtf(var + 1e-5f);
    const float4 g = ((const float4*)gamma)[tid];
    const float4 be = ((const float4*)beta)[tid];
    float4 o;
    o.x = (t0 - mu) * rstd * g.x + be.x;
    o.y = (t1 - mu) * rstd * g.y + be.y;
    o.z = (t2 - mu) * rstd * g.z + be.z;
    o.w = (t3 - mu) * rstd * g.w + be.w;
    ((float4*)(ln + (size_t)row * CD))[tid] = o;
}

extern "C" void kernel_launch(void* const* d_in, const int* in_sizes, int n_in,
                              void* d_out, int out_size) {
    const int*   eseq  = (const int*)d_in[0];
    const int*   dseq  = (const int*)d_in[1];
    const float* eemb  = (const float*)d_in[2];
    const float* demb  = (const float*)d_in[3];
    const float* Wih_f = (const float*)d_in[4];
    const float* Whh_f = (const float*)d_in[5];
    const float* bih_f = (const float*)d_in[6];
    const float* bhh_f = (const float*)d_in[7];
    const float* Wih_b = (const float*)d_in[8];
    const float* Whh_b = (const float*)d_in[9];
    const float* bih_b = (const float*)d_in[10];
    const float* bhh_b = (const float*)d_in[11];
    const float* Wih_d = (const float*)d_in[12];
    const float* Whh_d = (const float*)d_in[13];
    const float* bih_d = (const float*)d_in[14];
    const float* bhh_d = (const float*)d_in[15];
    const float* Wq = (const float*)d_in[16];
    const float* bq = (const float*)d_in[17];
    const float* Wk = (const float*)d_in[18];
    const float* bk = (const float*)d_in[19];
    const float* Wv = (const float*)d_in[20];
    const float* bv = (const float*)d_in[21];
    const float* Wfc = (const float*)d_in[22];
    const float* bfc = (const float*)d_in[23];
    const float* gamma = (const float*)d_in[24];
    const float* beta  = (const float*)d_in[25];
    float* out = (float*)d_out;

    float* S = nullptr;
    cudaGetSymbolAddress((void**)&S, g_scratch);
    float* xe  = S + OFF_XE;
    float* xd  = S + OFF_XD;
    float* xgf = S + OFF_XGF;
    float* xgb = S + OFF_XGB;
    float* xgd = S + OFF_XGD;
    float* enc = S + OFF_ENC;
    float* dec = S + OFF_DEC;
    float* q   = S + OFF_Q;
    float* k   = S + OFF_K;
    float* v   = S + OFF_V;
    float* ctx = S + OFF_CTX;
    float* ln  = S + OFF_LN;
    float* heb = S + OFF_HE;
    float* hdb = S + OFF_HD;
    float* cdi = S + OFF_CDI;

    cudaFuncSetAttribute(dec_rnn_kernel,
                         cudaFuncAttributeMaxDynamicSharedMemorySize, CD * CB * 4);
    cudaFuncSetAttribute(gemm_tc_kernel,
                         cudaFuncAttributeMaxDynamicSharedMemorySize, GEMM_SMEM);

    const int M = CB * CTE;  // 2048 (== CB*CTD)

    embed_kernel<<<CB * CTE + CB * CTD, 128>>>(eseq, dseq, eemb, demb, xe, xd);

    // input-gate GEMMs: xg = x @ Wih^T + bih + bhh
    gemm_tc_kernel<<<dim3(M/BM, 4*CH/BN), 256, GEMM_SMEM>>>(xe, Wih_f, bih_f, bhh_f, xgf, 4*CH, CE);
    gemm_tc_kernel<<<dim3(M/BM, 4*CH/BN), 256, GEMM_SMEM>>>(xe, Wih_b, bih_b, bhh_b, xgb, 4*CH, CE);
    gemm_tc_kernel<<<dim3(M/BM, 4*CD/BN), 256, GEMM_SMEM>>>(xd, Wih_d, bih_d, bhh_d, xgd, 4*CD, CE);

    enc_rnn_kernel<<<128, 128>>>(Whh_f, Whh_b, xgf, xgb, enc, heb, hdb, cdi);
    dec_rnn_kernel<<<128, 128, CD * CB * 4>>>(Whh_d, xgd, dec, hdb, cdi);

    gemm_tc_kernel<<<dim3(M/BM, CD/BN), 256, GEMM_SMEM>>>(dec, Wq, bq, nullptr, q, CD, CD);
    gemm_tc_kernel<<<dim3(M/BM, CD/BN), 256, GEMM_SMEM>>>(enc, Wk, bk, nullptr, k, CD, CD);
    gemm_tc_kernel<<<dim3(M/BM, CD/BN), 256, GEMM_SMEM>>>(enc, Wv, bv, nullptr, v, CD, CD);

    attn_kernel<<<CB * CTD, 128>>>(eseq, q, k, v, ctx);
    tanh_ln_kernel<<<CB * CTD, 256>>>(dec, ctx, gamma, beta, ln);

    gemm_tc_kernel<<<dim3(M/BM, CV/BN), 256, GEMM_SMEM>>>(ln, Wfc, bfc, nullptr, out, CV, CD);
}

// round 5
// speedup vs baseline: 1.2816x; 1.0046x over previous
#include <cuda_runtime.h>
#include <math.h>
#include <stdint.h>

#define CB   16
#define CTE  128
#define CTD  128
#define CE   512
#define CH   512
#define CD   1024
#define CV   32000

// ---- scratch layout (floats) ----
#define OFF_XE   ((size_t)0)
#define SZ_XE    ((size_t)CB*CTE*CE)
#define OFF_XD   (OFF_XE + SZ_XE)
#define SZ_XD    ((size_t)CB*CTD*CE)
#define OFF_XGF  (OFF_XD + SZ_XD)
#define SZ_XGF   ((size_t)CB*CTE*4*CH)
#define OFF_XGB  (OFF_XGF + SZ_XGF)
#define SZ_XGB   ((size_t)CB*CTE*4*CH)
#define OFF_XGD  (OFF_XGB + SZ_XGB)
#define SZ_XGD   ((size_t)CB*CTD*4*CD)
#define OFF_ENC  (OFF_XGD + SZ_XGD)
#define SZ_ENC   ((size_t)CB*CTE*CD)
#define OFF_DEC  (OFF_ENC + SZ_ENC)
#define SZ_DEC   ((size_t)CB*CTD*CD)
#define OFF_Q    (OFF_DEC + SZ_DEC)
#define SZ_Q     ((size_t)CB*CTD*CD)
#define OFF_K    (OFF_Q + SZ_Q)
#define SZ_K     ((size_t)CB*CTE*CD)
#define OFF_V    (OFF_K + SZ_K)
#define SZ_V     ((size_t)CB*CTE*CD)
#define OFF_CTX  (OFF_V + SZ_V)
#define SZ_CTX   ((size_t)CB*CTD*CD)
#define OFF_LN   (OFF_CTX + SZ_CTX)
#define SZ_LN    ((size_t)CB*CTD*CD)
#define OFF_HE   (OFF_LN + SZ_LN)
#define SZ_HE    ((size_t)2*2*CH*CB)
#define OFF_HD   (OFF_HE + SZ_HE)
#define SZ_HD    ((size_t)2*CD*CB)
#define OFF_CDI  (OFF_HD + SZ_HD)
#define SZ_CDI   ((size_t)CD*CB)
#define SCRATCH_TOTAL (OFF_CDI + SZ_CDI)

__device__ float g_scratch[SCRATCH_TOTAL];
__device__ unsigned g_bar_arrive;
__device__ unsigned g_bar_release;

__device__ __forceinline__ unsigned ld_acq_gpu(const unsigned* p) {
    unsigned v;
    asm volatile("ld.acquire.gpu.global.b32 %0, [%1];" : "=r"(v) : "l"(p) : "memory");
    return v;
}
__device__ __forceinline__ void st_rel_gpu(unsigned* p, unsigned v) {
    asm volatile("st.release.gpu.global.b32 [%0], %1;" :: "l"(p), "r"(v) : "memory");
}

// Grid-wide barrier for fully-resident grids (<=148 CTAs). No nanosleep:
// tight ld.acquire spin (each poll is an L2 round trip, self-throttling).
__device__ __forceinline__ void grid_sync_dev(unsigned nb) {
    __syncthreads();
    if (threadIdx.x == 0) {
        __threadfence();  // make this CTA's .cg stores visible before arrive
        unsigned gen = ld_acq_gpu(&g_bar_release);
        if (atomicAdd(&g_bar_arrive, 1u) == nb - 1u) {
            g_bar_arrive = 0u;
            st_rel_gpu(&g_bar_release, gen + 1u);
        } else {
            while (ld_acq_gpu(&g_bar_release) == gen) {}
        }
    }
    __syncthreads();
}

__device__ __forceinline__ float sigmoidf_(float x) { return 1.0f / (1.0f + expf(-x)); }

__device__ __forceinline__ uint32_t smem_u32(const void* p) {
    uint32_t a;
    asm("{ .reg .u64 t; cvta.to.shared.u64 t, %1; cvt.u32.u64 %0, t; }" : "=r"(a) : "l"(p));
    return a;
}
__device__ __forceinline__ void cp_async16(uint32_t dst, const void* src) {
    asm volatile("cp.async.cg.shared.global [%0], [%1], 16;" :: "r"(dst), "l"(src));
}
__device__ __forceinline__ void cp_commit() { asm volatile("cp.async.commit_group;" ::: "memory"); }
__device__ __forceinline__ uint32_t f2tf32(float f) {
    uint32_t u;
    asm("cvt.rna.tf32.f32 %0, %1;" : "=r"(u) : "f"(f));
    return u;
}
__device__ __forceinline__ void mma_tf32(float* c, const uint32_t* a, const uint32_t* b) {
    asm volatile(
        "mma.sync.aligned.m16n8k8.row.col.f32.tf32.tf32.f32 "
        "{%0,%1,%2,%3}, {%4,%5,%6,%7}, {%8,%9}, {%0,%1,%2,%3};"
        : "+f"(c[0]), "+f"(c[1]), "+f"(c[2]), "+f"(c[3])
        : "r"(a[0]), "r"(a[1]), "r"(a[2]), "r"(a[3]), "r"(b[0]), "r"(b[1]));
}

// ===================== tf32 mma.sync GEMM =====================
// C[M,N] = A[M,K] @ W[N,K]^T + bias1[n] (+bias2[n])
// BM=128, BN=128, BK=32, 256 threads = 8 warps (2m x 4n), warp tile 64x32.
#define BM 128
#define BN 128
#define GBK 32
#define GST 3
#define PADK 36
#define TILE_F (128 * PADK)
#define GEMM_SMEM (GST * 2 * TILE_F * 4)

__global__ void __launch_bounds__(256) gemm_tc_kernel(
    const float* __restrict__ A, const float* __restrict__ W,
    const float* __restrict__ bias1, const float* __restrict__ bias2,
    float* __restrict__ C, int N, int K)
{
    extern __shared__ float dsm[];
    float* sA = dsm;
    float* sB = dsm + GST * TILE_F;

    const int tid  = threadIdx.x;
    const int warp = tid >> 5;
    const int lane = tid & 31;
    const int g    = lane >> 2;
    const int tig  = lane & 3;
    const int wm   = warp >> 2;
    const int wn   = warp & 3;
    const int m0   = blockIdx.x * BM;
    const int n0   = blockIdx.y * BN;
    const int nst  = K / GBK;

    const uint32_t sA_u = smem_u32(sA);
    const uint32_t sB_u = smem_u32(sB);

    float acc[4][4][4];
#pragma unroll
    for (int i = 0; i < 4; i++)
#pragma unroll
        for (int j = 0; j < 4; j++)
#pragma unroll
            for (int r = 0; r < 4; r++) acc[i][j][r] = 0.0f;

    auto load_stage = [&](int kidx, int s) {
        const float* Ag = A + (size_t)m0 * K + kidx * GBK;
        const float* Wg = W + (size_t)n0 * K + kidx * GBK;
        uint32_t aBase = sA_u + (uint32_t)(s * TILE_F * 4);
        uint32_t bBase = sB_u + (uint32_t)(s * TILE_F * 4);
#pragma unroll
        for (int q = 0; q < 4; q++) {
            int ch = q * 256 + tid;
            int r = ch >> 3, c = ch & 7;
            cp_async16(aBase + (uint32_t)((r * PADK + c * 4) * 4),
                       Ag + (size_t)r * K + c * 4);
        }
#pragma unroll
        for (int q = 0; q < 4; q++) {
            int ch = q * 256 + tid;
            int r = ch >> 3, c = ch & 7;
            cp_async16(bBase + (uint32_t)((r * PADK + c * 4) * 4),
                       Wg + (size_t)r * K + c * 4);
        }
        cp_commit();
    };

    load_stage(0, 0);
    load_stage(1, 1);

    for (int i = 0; i < nst; i++) {
        if (i + 2 < nst) {
            load_stage(i + 2, (i + 2) % GST);
            asm volatile("cp.async.wait_group 2;" ::: "memory");
        } else if (i + 1 < nst) {
            asm volatile("cp.async.wait_group 1;" ::: "memory");
        } else {
            asm volatile("cp.async.wait_group 0;" ::: "memory");
        }
        __syncthreads();

        const int s = i % GST;
        const float* aS = sA + s * TILE_F;
        const float* bS = sB + s * TILE_F;

#pragma unroll
        for (int ks = 0; ks < 4; ks++) {
            const int kc = ks * 8 + tig;
            uint32_t af[4][4], bf[4][2];
#pragma unroll
            for (int mt = 0; mt < 4; mt++) {
                int row = wm * 64 + mt * 16 + g;
                af[mt][0] = f2tf32(aS[row * PADK + kc]);
                af[mt][1] = f2tf32(aS[(row + 8) * PADK + kc]);
                af[mt][2] = f2tf32(aS[row * PADK + kc + 4]);
                af[mt][3] = f2tf32(aS[(row + 8) * PADK + kc + 4]);
            }
#pragma unroll
            for (int nt = 0; nt < 4; nt++) {
                int n = wn * 32 + nt * 8 + g;
                bf[nt][0] = f2tf32(bS[n * PADK + kc]);
                bf[nt][1] = f2tf32(bS[n * PADK + kc + 4]);
            }
#pragma unroll
            for (int mt = 0; mt < 4; mt++)
#pragma unroll
                for (int nt = 0; nt < 4; nt++)
                    mma_tf32(acc[mt][nt], af[mt], bf[nt]);
        }
        __syncthreads();
    }

#pragma unroll
    for (int nt = 0; nt < 4; nt++) {
        int cn = n0 + wn * 32 + nt * 8 + 2 * tig;
        float b0 = bias1 ? bias1[cn] : 0.0f;
        float b1 = bias1 ? bias1[cn + 1] : 0.0f;
        if (bias2) { b0 += bias2[cn]; b1 += bias2[cn + 1]; }
#pragma unroll
        for (int mt = 0; mt < 4; mt++) {
            int r = m0 + wm * 64 + mt * 16 + g;
            float2 o0 = make_float2(acc[mt][nt][0] + b0, acc[mt][nt][1] + b1);
            float2 o1 = make_float2(acc[mt][nt][2] + b0, acc[mt][nt][3] + b1);
            *(float2*)(C + (size_t)r * N + cn) = o0;
            *(float2*)(C + (size_t)(r + 8) * N + cn) = o1;
        }
    }
}

// ---- embedding gather ----
__global__ void __launch_bounds__(128) embed_kernel(
    const int* __restrict__ eseq, const int* __restrict__ dseq,
    const float* __restrict__ eemb, const float* __restrict__ demb,
    float* __restrict__ xe, float* __restrict__ xd)
{
    int r = blockIdx.x;
    if (r < CB * CTE) {
        int tok = eseq[r];
        ((float4*)(xe + (size_t)r * CE))[threadIdx.x] =
            ((const float4*)(eemb + (size_t)tok * CE))[threadIdx.x];
    } else {
        int r2 = r - CB * CTE;
        int tok = dseq[r2];
        ((float4*)(xd + (size_t)r2 * CE))[threadIdx.x] =
            ((const float4*)(demb + (size_t)tok * CE))[threadIdx.x];
    }
}

// ---- bidirectional encoder recurrence: 128 CTAs (0-63 fwd, 64-127 bwd) ----
__global__ void __launch_bounds__(128) enc_rnn_kernel(
    const float* __restrict__ Whh_f, const float* __restrict__ Whh_b,
    const float* __restrict__ xgf, const float* __restrict__ xgb,
    float* __restrict__ enc, float* __restrict__ hebuf,
    float* __restrict__ hd0, float* __restrict__ cdi)
{
    __shared__ float sh[CH * CB];
    const int tid = threadIdx.x;
    const int b = tid & 15, ul = tid >> 4;
    const int dir = blockIdx.x >> 6;
    const int u = (blockIdx.x & 63) * 8 + ul;

    const float* Whh = dir ? Whh_b : Whh_f;
    const float* xg  = dir ? xgb : xgf;
    const float4* w0 = (const float4*)(Whh + (size_t)u * CH);
    const float4* w1 = (const float4*)(Whh + (size_t)(CH + u) * CH);
    const float4* w2 = (const float4*)(Whh + (size_t)(2 * CH + u) * CH);
    const float4* w3 = (const float4*)(Whh + (size_t)(3 * CH + u) * CH);

    float c = 0.0f, h = 0.0f;
    __stcg(&hebuf[(size_t)(0 * 2 + dir) * (CH * CB) + u * CB + b], 0.0f);
    grid_sync_dev(gridDim.x);

    for (int t = 0; t < CTE; t++) {
        const int cur = t & 1;
        {
            const float4* src = (const float4*)(hebuf + (size_t)(cur * 2 + dir) * (CH * CB));
            float4* dst = (float4*)sh;
#pragma unroll
            for (int i = 0; i < (CH * CB / 4) / 128; i++)
                dst[tid + i * 128] = __ldcg(&src[tid + i * 128]);
        }
        __syncthreads();

        const int te = dir ? (CTE - 1 - t) : t;
        size_t xb = ((size_t)(b * CTE + te)) * (4 * CH) + u;
        float a0 = xg[xb], a1 = xg[xb + CH], a2 = xg[xb + 2 * CH], a3 = xg[xb + 3 * CH];

#pragma unroll 4
        for (int k4 = 0; k4 < CH / 4; k4++) {
            float4 wi = w0[k4], wf = w1[k4], wg = w2[k4], wo = w3[k4];
            const float* hp = sh + (k4 * 4) * CB + b;
            float h0 = hp[0], h1 = hp[CB], h2 = hp[2 * CB], h3 = hp[3 * CB];
            a0 = fmaf(wi.x,h0,a0); a0 = fmaf(wi.y,h1,a0); a0 = fmaf(wi.z,h2,a0); a0 = fmaf(wi.w,h3,a0);
            a1 = fmaf(wf.x,h0,a1); a1 = fmaf(wf.y,h1,a1); a1 = fmaf(wf.z,h2,a1); a1 = fmaf(wf.w,h3,a1);
            a2 = fmaf(wg.x,h0,a2); a2 = fmaf(wg.y,h1,a2); a2 = fmaf(wg.z,h2,a2); a2 = fmaf(wg.w,h3,a2);
            a3 = fmaf(wo.x,h0,a3); a3 = fmaf(wo.y,h1,a3); a3 = fmaf(wo.z,h2,a3); a3 = fmaf(wo.w,h3,a3);
        }

        float ig = sigmoidf_(a0), fg = sigmoidf_(a1);
        float gg = tanhf(a2),     og = sigmoidf_(a3);
        c = fg * c + ig * gg;
        h = og * tanhf(c);

        __stcg(&hebuf[(size_t)((cur ^ 1) * 2 + dir) * (CH * CB) + u * CB + b], h);
        enc[((size_t)(b * CTE + te)) * CD + dir * CH + u] = h;
        grid_sync_dev(gridDim.x);
    }

    __stcg(&hd0[(size_t)(dir * CH + u) * CB + b], h);
    __stcg(&cdi[(size_t)(dir * CH + u) * CB + b], c);
}

// ---- decoder recurrence: 128 CTAs, 64KB dynamic smem ----
__global__ void __launch_bounds__(128) dec_rnn_kernel(
    const float* __restrict__ Whh, const float* __restrict__ xg,
    float* __restrict__ dec, float* __restrict__ hbuf,
    const float* __restrict__ cinit)
{
    extern __shared__ float sh[];
    const int tid = threadIdx.x;
    const int b = tid & 15, ul = tid >> 4;
    const int u = blockIdx.x * 8 + ul;

    const float4* w0 = (const float4*)(Whh + (size_t)u * CD);
    const float4* w1 = (const float4*)(Whh + (size_t)(CD + u) * CD);
    const float4* w2 = (const float4*)(Whh + (size_t)(2 * CD + u) * CD);
    const float4* w3 = (const float4*)(Whh + (size_t)(3 * CD + u) * CD);

    float c = __ldcg(&cinit[(size_t)u * CB + b]);

    for (int t = 0; t < CTD; t++) {
        const int cur = t & 1;
        {
            const float4* src = (const float4*)(hbuf + (size_t)cur * (CD * CB));
            float4* dst = (float4*)sh;
#pragma unroll
            for (int i = 0; i < (CD * CB / 4) / 128; i++)
                dst[tid + i * 128] = __ldcg(&src[tid + i * 128]);
        }
        __syncthreads();

        size_t xb = ((size_t)(b * CTD + t)) * (4 * CD) + u;
        float a0 = xg[xb], a1 = xg[xb + CD], a2 = xg[xb + 2 * CD], a3 = xg[xb + 3 * CD];

#pragma unroll 2
        for (int k4 = 0; k4 < CD / 4; k4++) {
            float4 wi = w0[k4], wf = w1[k4], wg = w2[k4], wo = w3[k4];
            const float* hp = sh + (k4 * 4) * CB + b;
            float h0 = hp[0], h1 = hp[CB], h2 = hp[2 * CB], h3 = hp[3 * CB];
            a0 = fmaf(wi.x,h0,a0); a0 = fmaf(wi.y,h1,a0); a0 = fmaf(wi.z,h2,a0); a0 = fmaf(wi.w,h3,a0);
            a1 = fmaf(wf.x,h0,a1); a1 = fmaf(wf.y,h1,a1); a1 = fmaf(wf.z,h2,a1); a1 = fmaf(wf.w,h3,a1);
            a2 = fmaf(wg.x,h0,a2); a2 = fmaf(wg.y,h1,a2); a2 = fmaf(wg.z,h2,a2); a2 = fmaf(wg.w,h3,a2);
            a3 = fmaf(wo.x,h0,a3); a3 = fmaf(wo.y,h1,a3); a3 = fmaf(wo.z,h2,a3); a3 = fmaf(wo.w,h3,a3);
        }

        float ig = sigmoidf_(a0), fg = sigmoidf_(a1);
        float gg = tanhf(a2),     og = sigmoidf_(a3);
        c = fg * c + ig * gg;
        float h = og * tanhf(c);

        __stcg(&hbuf[(size_t)(cur ^ 1) * (CD * CB) + (size_t)u * CB + b], h);
        dec[((size_t)(b * CTD + t)) * CD + u] = h;
        grid_sync_dev(gridDim.x);
    }
}

// ---- fused attention: one block per (b, qt) ----
__global__ void __launch_bounds__(128) attn_kernel(
    const int* __restrict__ eseq,
    const float* __restrict__ q, const float* __restrict__ k,
    const float* __restrict__ v, float* __restrict__ ctx)
{
    __shared__ float qs[CD];
    __shared__ float att[CTE];
    __shared__ float red[128];
    const int tid = threadIdx.x;
    const int b = blockIdx.x >> 7, qt = blockIdx.x & 127;
    const size_t qrow = (size_t)(b * CTD + qt) * CD;

    ((float4*)qs)[tid]       = ((const float4*)(q + qrow))[tid];
    ((float4*)qs)[tid + 128] = ((const float4*)(q + qrow))[tid + 128];
    __syncthreads();

    const float4* kr = (const float4*)(k + (size_t)(b * CTE + tid) * CD);
    float s = 0.0f;
#pragma unroll 8
    for (int k4 = 0; k4 < CD / 4; k4++) {
        float4 kv = kr[k4];
        s = fmaf(qs[k4*4+0], kv.x, s); s = fmaf(qs[k4*4+1], kv.y, s);
        s = fmaf(qs[k4*4+2], kv.z, s); s = fmaf(qs[k4*4+3], kv.w, s);
    }
    s *= 0.03125f;
    if (eseq[b * CTE + tid] == 0) s = -1e30f;

    red[tid] = s; __syncthreads();
#pragma unroll
    for (int o = 64; o > 0; o >>= 1) {
        if (tid < o) red[tid] = fmaxf(red[tid], red[tid + o]);
        __syncthreads();
    }
    float mx = red[0]; __syncthreads();
    float e = expf(s - mx);
    red[tid] = e; __syncthreads();
#pragma unroll
    for (int o = 64; o > 0; o >>= 1) {
        if (tid < o) red[tid] += red[tid + o];
        __syncthreads();
    }
    att[tid] = e / red[0];
    __syncthreads();

    float acc[8] = {0,0,0,0,0,0,0,0};
    for (int kt = 0; kt < CTE; kt++) {
        float a = att[kt];
        const float* vr = v + (size_t)(b * CTE + kt) * CD;
#pragma unroll
        for (int j = 0; j < 8; j++) acc[j] = fmaf(a, vr[tid + j * 128], acc[j]);
    }
    float* cr = ctx + (size_t)(b * CTD + qt) * CD;
#pragma unroll
    for (int j = 0; j < 8; j++) cr[tid + j * 128] = acc[j];
}

// ---- tanh(dec + ctx) -> layernorm ----
__global__ void __launch_bounds__(256) tanh_ln_kernel(
    const float* __restrict__ dec, const float* __restrict__ ctx,
    const float* __restrict__ gamma, const float* __restrict__ beta,
    float* __restrict__ ln)
{
    __shared__ float rs[8], rss[8];
    const int tid = threadIdx.x;
    const int row = blockIdx.x;
    const float4 a = ((const float4*)(dec + (size_t)row * CD))[tid];
    const float4 b = ((const float4*)(ctx + (size_t)row * CD))[tid];
    float t0 = tanhf(a.x + b.x), t1 = tanhf(a.y + b.y);
    float t2 = tanhf(a.z + b.z), t3 = tanhf(a.w + b.w);
    float s = t0 + t1 + t2 + t3;
    float ss = t0*t0 + t1*t1 + t2*t2 + t3*t3;
#pragma unroll
    for (int o = 16; o > 0; o >>= 1) {
        s  += __shfl_xor_sync(0xffffffffu, s, o);
        ss += __shfl_xor_sync(0xffffffffu, ss, o);
    }
    if ((tid & 31) == 0) { rs[tid >> 5] = s; rss[tid >> 5] = ss; }
    __syncthreads();
    if (tid < 8) { s = rs[tid]; ss = rss[tid]; }
    else { s = 0; ss = 0; }
    if (tid < 32) {
#pragma unroll
        for (int o = 4; o > 0; o >>= 1) {
            s  += __shfl_xor_sync(0xffffffffu, s, o);
            ss += __shfl_xor_sync(0xffffffffu, ss, o);
        }
        if (tid == 0) { rs[0] = s; rss[0] = ss; }
    }
    __syncthreads();
    float mu = rs[0] * (1.0f / CD);
    float var = rss[0] * (1.0f / CD) - mu * mu;
    float rstd = rsqrtf(var + 1e-5f);
    const float4 g = ((const float4*)gamma)[tid];
    const float4 be = ((const float4*)beta)[tid];
    float4 o;
    o.x = (t0 - mu) * rstd * g.x + be.x;
    o.y = (t1 - mu) * rstd * g.y + be.y;
    o.z = (t2 - mu) * rstd * g.z + be.z;
    o.w = (t3 - mu) * rstd * g.w + be.w;
    ((float4*)(ln + (size_t)row * CD))[tid] = o;
}

extern "C" void kernel_launch(void* const* d_in, const int* in_sizes, int n_in,
                              void* d_out, int out_size) {
    const int*   eseq  = (const int*)d_in[0];
    const int*   dseq  = (const int*)d_in[1];
    const float* eemb  = (const float*)d_in[2];
    const float* demb  = (const float*)d_in[3];
    const float* Wih_f = (const float*)d_in[4];
    const float* Whh_f = (const float*)d_in[5];
    const float* bih_f = (const float*)d_in[6];
    const float* bhh_f = (const float*)d_in[7];
    const float* Wih_b = (const float*)d_in[8];
    const float* Whh_b = (const float*)d_in[9];
    const float* bih_b = (const float*)d_in[10];
    const float* bhh_b = (const float*)d_in[11];
    const float* Wih_d = (const float*)d_in[12];
    const float* Whh_d = (const float*)d_in[13];
    const float* bih_d = (const float*)d_in[14];
    const float* bhh_d = (const float*)d_in[15];
    const float* Wq = (const float*)d_in[16];
    const float* bq = (const float*)d_in[17];
    const float* Wk = (const float*)d_in[18];
    const float* bk = (const float*)d_in[19];
    const float* Wv = (const float*)d_in[20];
    const float* bv = (const float*)d_in[21];
    const float* Wfc = (const float*)d_in[22];
    const float* bfc = (const float*)d_in[23];
    const float* gamma = (const float*)d_in[24];
    const float* beta  = (const float*)d_in[25];
    float* out = (float*)d_out;

    float* S = nullptr;
    cudaGetSymbolAddress((void**)&S, g_scratch);
    float* xe  = S + OFF_XE;
    float* xd  = S + OFF_XD;
    float* xgf = S + OFF_XGF;
    float* xgb = S + OFF_XGB;
    float* xgd = S + OFF_XGD;
    float* enc = S + OFF_ENC;
    float* dec = S + OFF_DEC;
    float* q   = S + OFF_Q;
    float* k   = S + OFF_K;
    float* v   = S + OFF_V;
    float* ctx = S + OFF_CTX;
    float* ln  = S + OFF_LN;
    float* heb = S + OFF_HE;
    float* hdb = S + OFF_HD;
    float* cdi = S + OFF_CDI;

    cudaFuncSetAttribute(dec_rnn_kernel,
                         cudaFuncAttributeMaxDynamicSharedMemorySize, CD * CB * 4);
    cudaFuncSetAttribute(gemm_tc_kernel,
                         cudaFuncAttributeMaxDynamicSharedMemorySize, GEMM_SMEM);

    const int M = CB * CTE;  // 2048 (== CB*CTD)

    embed_kernel<<<CB * CTE + CB * CTD, 128>>>(eseq, dseq, eemb, demb, xe, xd);

    gemm_tc_kernel<<<dim3(M/BM, 4*CH/BN), 256, GEMM_SMEM>>>(xe, Wih_f, bih_f, bhh_f, xgf, 4*CH, CE);
    gemm_tc_kernel<<<dim3(M/BM, 4*CH/BN), 256, GEMM_SMEM>>>(xe, Wih_b, bih_b, bhh_b, xgb, 4*CH, CE);
    gemm_tc_kernel<<<dim3(M/BM, 4*CD/BN), 256, GEMM_SMEM>>>(xd, Wih_d, bih_d, bhh_d, xgd, 4*CD, CE);

    enc_rnn_kernel<<<128, 128>>>(Whh_f, Whh_b, xgf, xgb, enc, heb, hdb, cdi);
    dec_rnn_kernel<<<128, 128, CD * CB * 4>>>(Whh_d, xgd, dec, hdb, cdi);

    gemm_tc_kernel<<<dim3(M/BM, CD/BN), 256, GEMM_SMEM>>>(dec, Wq, bq, nullptr, q, CD, CD);
    gemm_tc_kernel<<<dim3(M/BM, CD/BN), 256, GEMM_SMEM>>>(enc, Wk, bk, nullptr, k, CD, CD);
    gemm_tc_kernel<<<dim3(M/BM, CD/BN), 256, GEMM_SMEM>>>(enc, Wv, bv, nullptr, v, CD, CD);

    attn_kernel<<<CB * CTD, 128>>>(eseq, q, k, v, ctx);
    tanh_ln_kernel<<<CB * CTD, 256>>>(dec, ctx, gamma, beta, ln);

    gemm_tc_kernel<<<dim3(M/BM, CV/BN), 256, GEMM_SMEM>>>(ln, Wfc, bfc, nullptr, out, CV, CD);
}

// round 6
// speedup vs baseline: 2.5407x; 1.9825x over previous
#include <cuda_runtime.h>
#include <math.h>
#include <stdint.h>

#define CB   16
#define CTE  128
#define CTD  128
#define CE   512
#define CH   512
#define CD   1024
#define CV   32000

// ---- scratch layout (floats) ----
#define OFF_XE   ((size_t)0)
#define SZ_XE    ((size_t)CB*CTE*CE)
#define OFF_XD   (OFF_XE + SZ_XE)
#define SZ_XD    ((size_t)CB*CTD*CE)
#define OFF_XGF  (OFF_XD + SZ_XD)
#define SZ_XGF   ((size_t)CB*CTE*4*CH)
#define OFF_XGB  (OFF_XGF + SZ_XGF)
#define SZ_XGB   ((size_t)CB*CTE*4*CH)
#define OFF_XGD  (OFF_XGB + SZ_XGB)
#define SZ_XGD   ((size_t)CB*CTD*4*CD)
#define OFF_ENC  (OFF_XGD + SZ_XGD)
#define SZ_ENC   ((size_t)CB*CTE*CD)
#define OFF_DEC  (OFF_ENC + SZ_ENC)
#define SZ_DEC   ((size_t)CB*CTD*CD)
#define OFF_Q    (OFF_DEC + SZ_DEC)
#define SZ_Q     ((size_t)CB*CTD*CD)
#define OFF_K    (OFF_Q + SZ_Q)
#define SZ_K     ((size_t)CB*CTE*CD)
#define OFF_V    (OFF_K + SZ_K)
#define SZ_V     ((size_t)CB*CTE*CD)
#define OFF_CTX  (OFF_V + SZ_V)
#define SZ_CTX   ((size_t)CB*CTD*CD)
#define OFF_LN   (OFF_CTX + SZ_CTX)
#define SZ_LN    ((size_t)CB*CTD*CD)
#define OFF_HE   (OFF_LN + SZ_LN)
#define SZ_HE    ((size_t)2*2*CH*CB)
#define OFF_HD   (OFF_HE + SZ_HE)
#define SZ_HD    ((size_t)2*CD*CB)
#define OFF_CDI  (OFF_HD + SZ_HD)
#define SZ_CDI   ((size_t)CD*CB)
#define SCRATCH_TOTAL (OFF_CDI + SZ_CDI)

__device__ float g_scratch[SCRATCH_TOTAL];
__device__ unsigned g_bar_arrive;
__device__ unsigned g_bar_release;

__device__ __forceinline__ unsigned ld_acq_gpu(const unsigned* p) {
    unsigned v;
    asm volatile("ld.acquire.gpu.global.b32 %0, [%1];" : "=r"(v) : "l"(p) : "memory");
    return v;
}
__device__ __forceinline__ void st_rel_gpu(unsigned* p, unsigned v) {
    asm volatile("st.release.gpu.global.b32 [%0], %1;" :: "l"(p), "r"(v) : "memory");
}

__device__ __forceinline__ void grid_sync_dev(unsigned nb) {
    __syncthreads();
    if (threadIdx.x == 0) {
        __threadfence();
        unsigned gen = ld_acq_gpu(&g_bar_release);
        if (atomicAdd(&g_bar_arrive, 1u) == nb - 1u) {
            g_bar_arrive = 0u;
            st_rel_gpu(&g_bar_release, gen + 1u);
        } else {
            while (ld_acq_gpu(&g_bar_release) == gen) {}
        }
    }
    __syncthreads();
}

__device__ __forceinline__ float sigmoidf_(float x) { return 1.0f / (1.0f + expf(-x)); }

__device__ __forceinline__ uint32_t smem_u32(const void* p) {
    uint32_t a;
    asm("{ .reg .u64 t; cvta.to.shared.u64 t, %1; cvt.u32.u64 %0, t; }" : "=r"(a) : "l"(p));
    return a;
}
__device__ __forceinline__ void cp_async16(uint32_t dst, const void* src) {
    asm volatile("cp.async.cg.shared.global [%0], [%1], 16;" :: "r"(dst), "l"(src));
}
__device__ __forceinline__ void cp_commit() { asm volatile("cp.async.commit_group;" ::: "memory"); }
__device__ __forceinline__ uint32_t f2tf32(float f) {
    uint32_t u;
    asm("cvt.rna.tf32.f32 %0, %1;" : "=r"(u) : "f"(f));
    return u;
}
__device__ __forceinline__ void mma_tf32(float* c, const uint32_t* a, const uint32_t* b) {
    asm volatile(
        "mma.sync.aligned.m16n8k8.row.col.f32.tf32.tf32.f32 "
        "{%0,%1,%2,%3}, {%4,%5,%6,%7}, {%8,%9}, {%0,%1,%2,%3};"
        : "+f"(c[0]), "+f"(c[1]), "+f"(c[2]), "+f"(c[3])
        : "r"(a[0]), "r"(a[1]), "r"(a[2]), "r"(a[3]), "r"(b[0]), "r"(b[1]));
}

// ===================== tf32 mma.sync GEMM (unchanged from R5) =====================
#define BM 128
#define BN 128
#define GBK 32
#define GST 3
#define PADK 36
#define TILE_F (128 * PADK)
#define GEMM_SMEM (GST * 2 * TILE_F * 4)

__global__ void __launch_bounds__(256) gemm_tc_kernel(
    const float* __restrict__ A, const float* __restrict__ W,
    const float* __restrict__ bias1, const float* __restrict__ bias2,
    float* __restrict__ C, int N, int K)
{
    extern __shared__ float dsm[];
    float* sA = dsm;
    float* sB = dsm + GST * TILE_F;

    const int tid  = threadIdx.x;
    const int warp = tid >> 5;
    const int lane = tid & 31;
    const int g    = lane >> 2;
    const int tig  = lane & 3;
    const int wm   = warp >> 2;
    const int wn   = warp & 3;
    const int m0   = blockIdx.x * BM;
    const int n0   = blockIdx.y * BN;
    const int nst  = K / GBK;

    const uint32_t sA_u = smem_u32(sA);
    const uint32_t sB_u = smem_u32(sB);

    float acc[4][4][4];
#pragma unroll
    for (int i = 0; i < 4; i++)
#pragma unroll
        for (int j = 0; j < 4; j++)
#pragma unroll
            for (int r = 0; r < 4; r++) acc[i][j][r] = 0.0f;

    auto load_stage = [&](int kidx, int s) {
        const float* Ag = A + (size_t)m0 * K + kidx * GBK;
        const float* Wg = W + (size_t)n0 * K + kidx * GBK;
        uint32_t aBase = sA_u + (uint32_t)(s * TILE_F * 4);
        uint32_t bBase = sB_u + (uint32_t)(s * TILE_F * 4);
#pragma unroll
        for (int q = 0; q < 4; q++) {
            int ch = q * 256 + tid;
            int r = ch >> 3, c = ch & 7;
            cp_async16(aBase + (uint32_t)((r * PADK + c * 4) * 4),
                       Ag + (size_t)r * K + c * 4);
        }
#pragma unroll
        for (int q = 0; q < 4; q++) {
            int ch = q * 256 + tid;
            int r = ch >> 3, c = ch & 7;
            cp_async16(bBase + (uint32_t)((r * PADK + c * 4) * 4),
                       Wg + (size_t)r * K + c * 4);
        }
        cp_commit();
    };

    load_stage(0, 0);
    load_stage(1, 1);

    for (int i = 0; i < nst; i++) {
        if (i + 2 < nst) {
            load_stage(i + 2, (i + 2) % GST);
            asm volatile("cp.async.wait_group 2;" ::: "memory");
        } else if (i + 1 < nst) {
            asm volatile("cp.async.wait_group 1;" ::: "memory");
        } else {
            asm volatile("cp.async.wait_group 0;" ::: "memory");
        }
        __syncthreads();

        const int s = i % GST;
        const float* aS = sA + s * TILE_F;
        const float* bS = sB + s * TILE_F;

#pragma unroll
        for (int ks = 0; ks < 4; ks++) {
            const int kc = ks * 8 + tig;
            uint32_t af[4][4], bf[4][2];
#pragma unroll
            for (int mt = 0; mt < 4; mt++) {
                int row = wm * 64 + mt * 16 + g;
                af[mt][0] = f2tf32(aS[row * PADK + kc]);
                af[mt][1] = f2tf32(aS[(row + 8) * PADK + kc]);
                af[mt][2] = f2tf32(aS[row * PADK + kc + 4]);
                af[mt][3] = f2tf32(aS[(row + 8) * PADK + kc + 4]);
            }
#pragma unroll
            for (int nt = 0; nt < 4; nt++) {
                int n = wn * 32 + nt * 8 + g;
                bf[nt][0] = f2tf32(bS[n * PADK + kc]);
                bf[nt][1] = f2tf32(bS[n * PADK + kc + 4]);
            }
#pragma unroll
            for (int mt = 0; mt < 4; mt++)
#pragma unroll
                for (int nt = 0; nt < 4; nt++)
                    mma_tf32(acc[mt][nt], af[mt], bf[nt]);
        }
        __syncthreads();
    }

#pragma unroll
    for (int nt = 0; nt < 4; nt++) {
        int cn = n0 + wn * 32 + nt * 8 + 2 * tig;
        float b0 = bias1 ? bias1[cn] : 0.0f;
        float b1 = bias1 ? bias1[cn + 1] : 0.0f;
        if (bias2) { b0 += bias2[cn]; b1 += bias2[cn + 1]; }
#pragma unroll
        for (int mt = 0; mt < 4; mt++) {
            int r = m0 + wm * 64 + mt * 16 + g;
            float2 o0 = make_float2(acc[mt][nt][0] + b0, acc[mt][nt][1] + b1);
            float2 o1 = make_float2(acc[mt][nt][2] + b0, acc[mt][nt][3] + b1);
            *(float2*)(C + (size_t)r * N + cn) = o0;
            *(float2*)(C + (size_t)(r + 8) * N + cn) = o1;
        }
    }
}

// ---- embedding gather ----
__global__ void __launch_bounds__(128) embed_kernel(
    const int* __restrict__ eseq, const int* __restrict__ dseq,
    const float* __restrict__ eemb, const float* __restrict__ demb,
    float* __restrict__ xe, float* __restrict__ xd)
{
    int r = blockIdx.x;
    if (r < CB * CTE) {
        int tok = eseq[r];
        ((float4*)(xe + (size_t)r * CE))[threadIdx.x] =
            ((const float4*)(eemb + (size_t)tok * CE))[threadIdx.x];
    } else {
        int r2 = r - CB * CTE;
        int tok = dseq[r2];
        ((float4*)(xd + (size_t)r2 * CE))[threadIdx.x] =
            ((const float4*)(demb + (size_t)tok * CE))[threadIdx.x];
    }
}

// ---- bidirectional encoder recurrence: weights resident in smem ----
// per CTA: 8 units x 4 gates x CH floats, stride padded to shift banks per ul
#define EW_STRIDE (4 * CH + 4)                      // 2052 floats per ul
#define ENC_SMEM ((8 * EW_STRIDE + CH * CB) * 4)    // 65664 + 32768 = 98432 B

__global__ void __launch_bounds__(128) enc_rnn_kernel(
    const float* __restrict__ Whh_f, const float* __restrict__ Whh_b,
    const float* __restrict__ xgf, const float* __restrict__ xgb,
    float* __restrict__ enc, float* __restrict__ hebuf,
    float* __restrict__ hd0, float* __restrict__ cdi)
{
    extern __shared__ float sm[];
    float* wsm = sm;                    // [ul][g*CH + k]
    float* hsm = sm + 8 * EW_STRIDE;    // [k][b]

    const int tid = threadIdx.x;
    const int b = tid & 15, ul = tid >> 4;
    const int dir = blockIdx.x >> 6;
    const int u = (blockIdx.x & 63) * 8 + ul;
    const int ubase = (blockIdx.x & 63) * 8;

    const float* Whh = dir ? Whh_b : Whh_f;
    const float* xg  = dir ? xgb : xgf;

    // one-time weight load: 8 ul x 4 gates x 128 float4 = 4096 float4
    for (int i = tid; i < 4096; i += 128) {
        int ulw = i >> 9;
        int rem = i & 511;
        int gg = rem >> 7, k4 = rem & 127;
        float4 v = *(const float4*)(Whh + ((size_t)(gg * CH + ubase + ulw)) * CH + k4 * 4);
        *(float4*)(wsm + ulw * EW_STRIDE + gg * CH + k4 * 4) = v;
    }

    const float* wp = wsm + ul * EW_STRIDE;

    float c = 0.0f, h = 0.0f;
    __stcg(&hebuf[(size_t)(0 * 2 + dir) * (CH * CB) + u * CB + b], 0.0f);
    grid_sync_dev(gridDim.x);

    for (int t = 0; t < CTE; t++) {
        const int cur = t & 1;
        {
            const float4* src = (const float4*)(hebuf + (size_t)(cur * 2 + dir) * (CH * CB));
            float4* dst = (float4*)hsm;
#pragma unroll
            for (int i = 0; i < (CH * CB / 4) / 128; i++)
                dst[tid + i * 128] = __ldcg(&src[tid + i * 128]);
        }
        __syncthreads();

        const int te = dir ? (CTE - 1 - t) : t;
        size_t xb = ((size_t)(b * CTE + te)) * (4 * CH) + u;
        float a0 = xg[xb], a1 = xg[xb + CH], a2 = xg[xb + 2 * CH], a3 = xg[xb + 3 * CH];

#pragma unroll 4
        for (int k4 = 0; k4 < CH / 4; k4++) {
            float4 wi = *(const float4*)(wp + k4 * 4);
            float4 wf = *(const float4*)(wp + CH + k4 * 4);
            float4 wg = *(const float4*)(wp + 2 * CH + k4 * 4);
            float4 wo = *(const float4*)(wp + 3 * CH + k4 * 4);
            const float* hp = hsm + (k4 * 4) * CB + b;
            float h0 = hp[0], h1 = hp[CB], h2 = hp[2 * CB], h3 = hp[3 * CB];
            a0 = fmaf(wi.x,h0,a0); a0 = fmaf(wi.y,h1,a0); a0 = fmaf(wi.z,h2,a0); a0 = fmaf(wi.w,h3,a0);
            a1 = fmaf(wf.x,h0,a1); a1 = fmaf(wf.y,h1,a1); a1 = fmaf(wf.z,h2,a1); a1 = fmaf(wf.w,h3,a1);
            a2 = fmaf(wg.x,h0,a2); a2 = fmaf(wg.y,h1,a2); a2 = fmaf(wg.z,h2,a2); a2 = fmaf(wg.w,h3,a2);
            a3 = fmaf(wo.x,h0,a3); a3 = fmaf(wo.y,h1,a3); a3 = fmaf(wo.z,h2,a3); a3 = fmaf(wo.w,h3,a3);
        }

        float ig = sigmoidf_(a0), fg = sigmoidf_(a1);
        float gg = tanhf(a2),     og = sigmoidf_(a3);
        c = fg * c + ig * gg;
        h = og * tanhf(c);

        __stcg(&hebuf[(size_t)((cur ^ 1) * 2 + dir) * (CH * CB) + u * CB + b], h);
        enc[((size_t)(b * CTE + te)) * CD + dir * CH + u] = h;
        grid_sync_dev(gridDim.x);
    }

    __stcg(&hd0[(size_t)(dir * CH + u) * CB + b], h);
    __stcg(&cdi[(size_t)(dir * CH + u) * CB + b], c);
}

// ---- decoder recurrence: weights resident in smem ----
#define DW_STRIDE (4 * CD + 4)                      // 4100 floats per ul
#define DEC_SMEM ((8 * DW_STRIDE + CD * CB) * 4)    // 131200 + 65536 = 196736 B

__global__ void __launch_bounds__(128) dec_rnn_kernel(
    const float* __restrict__ Whh, const float* __restrict__ xg,
    float* __restrict__ dec, float* __restrict__ hbuf,
    const float* __restrict__ cinit)
{
    extern __shared__ float sm[];
    float* wsm = sm;                    // [ul][g*CD + k]
    float* hsm = sm + 8 * DW_STRIDE;    // [k][b]

    const int tid = threadIdx.x;
    const int b = tid & 15, ul = tid >> 4;
    const int u = blockIdx.x * 8 + ul;
    const int ubase = blockIdx.x * 8;

    // one-time weight load: 8 ul x 4 gates x 256 float4 = 8192 float4
    for (int i = tid; i < 8192; i += 128) {
        int ulw = i >> 10;
        int rem = i & 1023;
        int gg = rem >> 8, k4 = rem & 255;
        float4 v = *(const float4*)(Whh + ((size_t)(gg * CD + ubase + ulw)) * CD + k4 * 4);
        *(float4*)(wsm + ulw * DW_STRIDE + gg * CD + k4 * 4) = v;
    }

    const float* wp = wsm + ul * DW_STRIDE;

    float c = __ldcg(&cinit[(size_t)u * CB + b]);

    for (int t = 0; t < CTD; t++) {
        const int cur = t & 1;
        {
            const float4* src = (const float4*)(hbuf + (size_t)cur * (CD * CB));
            float4* dst = (float4*)hsm;
#pragma unroll
            for (int i = 0; i < (CD * CB / 4) / 128; i++)
                dst[tid + i * 128] = __ldcg(&src[tid + i * 128]);
        }
        __syncthreads();

        size_t xb = ((size_t)(b * CTD + t)) * (4 * CD) + u;
        float a0 = xg[xb], a1 = xg[xb + CD], a2 = xg[xb + 2 * CD], a3 = xg[xb + 3 * CD];

#pragma unroll 2
        for (int k4 = 0; k4 < CD / 4; k4++) {
            float4 wi = *(const float4*)(wp + k4 * 4);
            float4 wf = *(const float4*)(wp + CD + k4 * 4);
            float4 wg = *(const float4*)(wp + 2 * CD + k4 * 4);
            float4 wo = *(const float4*)(wp + 3 * CD + k4 * 4);
            const float* hp = hsm + (k4 * 4) * CB + b;
            float h0 = hp[0], h1 = hp[CB], h2 = hp[2 * CB], h3 = hp[3 * CB];
            a0 = fmaf(wi.x,h0,a0); a0 = fmaf(wi.y,h1,a0); a0 = fmaf(wi.z,h2,a0); a0 = fmaf(wi.w,h3,a0);
            a1 = fmaf(wf.x,h0,a1); a1 = fmaf(wf.y,h1,a1); a1 = fmaf(wf.z,h2,a1); a1 = fmaf(wf.w,h3,a1);
            a2 = fmaf(wg.x,h0,a2); a2 = fmaf(wg.y,h1,a2); a2 = fmaf(wg.z,h2,a2); a2 = fmaf(wg.w,h3,a2);
            a3 = fmaf(wo.x,h0,a3); a3 = fmaf(wo.y,h1,a3); a3 = fmaf(wo.z,h2,a3); a3 = fmaf(wo.w,h3,a3);
        }

        float ig = sigmoidf_(a0), fg = sigmoidf_(a1);
        float gg = tanhf(a2),     og = sigmoidf_(a3);
        c = fg * c + ig * gg;
        float h = og * tanhf(c);

        __stcg(&hbuf[(size_t)(cur ^ 1) * (CD * CB) + (size_t)u * CB + b], h);
        dec[((size_t)(b * CTD + t)) * CD + u] = h;
        grid_sync_dev(gridDim.x);
    }
}

// ---- fused attention: one block per (b, qt) ----
__global__ void __launch_bounds__(128) attn_kernel(
    const int* __restrict__ eseq,
    const float* __restrict__ q, const float* __restrict__ k,
    const float* __restrict__ v, float* __restrict__ ctx)
{
    __shared__ float qs[CD];
    __shared__ float att[CTE];
    __shared__ float red[128];
    const int tid = threadIdx.x;
    const int b = blockIdx.x >> 7, qt = blockIdx.x & 127;
    const size_t qrow = (size_t)(b * CTD + qt) * CD;

    ((float4*)qs)[tid]       = ((const float4*)(q + qrow))[tid];
    ((float4*)qs)[tid + 128] = ((const float4*)(q + qrow))[tid + 128];
    __syncthreads();

    const float4* kr = (const float4*)(k + (size_t)(b * CTE + tid) * CD);
    float s = 0.0f;
#pragma unroll 8
    for (int k4 = 0; k4 < CD / 4; k4++) {
        float4 kv = kr[k4];
        s = fmaf(qs[k4*4+0], kv.x, s); s = fmaf(qs[k4*4+1], kv.y, s);
        s = fmaf(qs[k4*4+2], kv.z, s); s = fmaf(qs[k4*4+3], kv.w, s);
    }
    s *= 0.03125f;
    if (eseq[b * CTE + tid] == 0) s = -1e30f;

    red[tid] = s; __syncthreads();
#pragma unroll
    for (int o = 64; o > 0; o >>= 1) {
        if (tid < o) red[tid] = fmaxf(red[tid], red[tid + o]);
        __syncthreads();
    }
    float mx = red[0]; __syncthreads();
    float e = expf(s - mx);
    red[tid] = e; __syncthreads();
#pragma unroll
    for (int o = 64; o > 0; o >>= 1) {
        if (tid < o) red[tid] += red[tid + o];
        __syncthreads();
    }
    att[tid] = e / red[0];
    __syncthreads();

    float acc[8] = {0,0,0,0,0,0,0,0};
    for (int kt = 0; kt < CTE; kt++) {
        float a = att[kt];
        const float* vr = v + (size_t)(b * CTE + kt) * CD;
#pragma unroll
        for (int j = 0; j < 8; j++) acc[j] = fmaf(a, vr[tid + j * 128], acc[j]);
    }
    float* cr = ctx + (size_t)(b * CTD + qt) * CD;
#pragma unroll
    for (int j = 0; j < 8; j++) cr[tid + j * 128] = acc[j];
}

// ---- tanh(dec + ctx) -> layernorm ----
__global__ void __launch_bounds__(256) tanh_ln_kernel(
    const float* __restrict__ dec, const float* __restrict__ ctx,
    const float* __restrict__ gamma, const float* __restrict__ beta,
    float* __restrict__ ln)
{
    __shared__ float rs[8], rss[8];
    const int tid = threadIdx.x;
    const int row = blockIdx.x;
    const float4 a = ((const float4*)(dec + (size_t)row * CD))[tid];
    const float4 b = ((const float4*)(ctx + (size_t)row * CD))[tid];
    float t0 = tanhf(a.x + b.x), t1 = tanhf(a.y + b.y);
    float t2 = tanhf(a.z + b.z), t3 = tanhf(a.w + b.w);
    float s = t0 + t1 + t2 + t3;
    float ss = t0*t0 + t1*t1 + t2*t2 + t3*t3;
#pragma unroll
    for (int o = 16; o > 0; o >>= 1) {
        s  += __shfl_xor_sync(0xffffffffu, s, o);
        ss += __shfl_xor_sync(0xffffffffu, ss, o);
    }
    if ((tid & 31) == 0) { rs[tid >> 5] = s; rss[tid >> 5] = ss; }
    __syncthreads();
    if (tid < 8) { s = rs[tid]; ss = rss[tid]; }
    else { s = 0; ss = 0; }
    if (tid < 32) {
#pragma unroll
        for (int o = 4; o > 0; o >>= 1) {
            s  += __shfl_xor_sync(0xffffffffu, s, o);
            ss += __shfl_xor_sync(0xffffffffu, ss, o);
        }
        if (tid == 0) { rs[0] = s; rss[0] = ss; }
    }
    __syncthreads();
    float mu = rs[0] * (1.0f / CD);
    float var = rss[0] * (1.0f / CD) - mu * mu;
    float rstd = rsqrtf(var + 1e-5f);
    const float4 g = ((const float4*)gamma)[tid];
    const float4 be = ((const float4*)beta)[tid];
    float4 o;
    o.x = (t0 - mu) * rstd * g.x + be.x;
    o.y = (t1 - mu) * rstd * g.y + be.y;
    o.z = (t2 - mu) * rstd * g.z + be.z;
    o.w = (t3 - mu) * rstd * g.w + be.w;
    ((float4*)(ln + (size_t)row * CD))[tid] = o;
}

extern "C" void kernel_launch(void* const* d_in, const int* in_sizes, int n_in,
                              void* d_out, int out_size) {
    const int*   eseq  = (const int*)d_in[0];
    const int*   dseq  = (const int*)d_in[1];
    const float* eemb  = (const float*)d_in[2];
    const float* demb  = (const float*)d_in[3];
    const float* Wih_f = (const float*)d_in[4];
    const float* Whh_f = (const float*)d_in[5];
    const float* bih_f = (const float*)d_in[6];
    const float* bhh_f = (const float*)d_in[7];
    const float* Wih_b = (const float*)d_in[8];
    const float* Whh_b = (const float*)d_in[9];
    const float* bih_b = (const float*)d_in[10];
    const float* bhh_b = (const float*)d_in[11];
    const float* Wih_d = (const float*)d_in[12];
    const float* Whh_d = (const float*)d_in[13];
    const float* bih_d = (const float*)d_in[14];
    const float* bhh_d = (const float*)d_in[15];
    const float* Wq = (const float*)d_in[16];
    const float* bq = (const float*)d_in[17];
    const float* Wk = (const float*)d_in[18];
    const float* bk = (const float*)d_in[19];
    const float* Wv = (const float*)d_in[20];
    const float* bv = (const float*)d_in[21];
    const float* Wfc = (const float*)d_in[22];
    const float* bfc = (const float*)d_in[23];
    const float* gamma = (const float*)d_in[24];
    const float* beta  = (const float*)d_in[25];
    float* out = (float*)d_out;

    float* S = nullptr;
    cudaGetSymbolAddress((void**)&S, g_scratch);
    float* xe  = S + OFF_XE;
    float* xd  = S + OFF_XD;
    float* xgf = S + OFF_XGF;
    float* xgb = S + OFF_XGB;
    float* xgd = S + OFF_XGD;
    float* enc = S + OFF_ENC;
    float* dec = S + OFF_DEC;
    float* q   = S + OFF_Q;
    float* k   = S + OFF_K;
    float* v   = S + OFF_V;
    float* ctx = S + OFF_CTX;
    float* ln  = S + OFF_LN;
    float* heb = S + OFF_HE;
    float* hdb = S + OFF_HD;
    float* cdi = S + OFF_CDI;

    cudaFuncSetAttribute(enc_rnn_kernel,
                         cudaFuncAttributeMaxDynamicSharedMemorySize, ENC_SMEM);
    cudaFuncSetAttribute(dec_rnn_kernel,
                         cudaFuncAttributeMaxDynamicSharedMemorySize, DEC_SMEM);
    cudaFuncSetAttribute(gemm_tc_kernel,
                         cudaFuncAttributeMaxDynamicSharedMemorySize, GEMM_SMEM);

    const int M = CB * CTE;  // 2048 (== CB*CTD)

    embed_kernel<<<CB * CTE + CB * CTD, 128>>>(eseq, dseq, eemb, demb, xe, xd);

    gemm_tc_kernel<<<dim3(M/BM, 4*CH/BN), 256, GEMM_SMEM>>>(xe, Wih_f, bih_f, bhh_f, xgf, 4*CH, CE);
    gemm_tc_kernel<<<dim3(M/BM, 4*CH/BN), 256, GEMM_SMEM>>>(xe, Wih_b, bih_b, bhh_b, xgb, 4*CH, CE);
    gemm_tc_kernel<<<dim3(M/BM, 4*CD/BN), 256, GEMM_SMEM>>>(xd, Wih_d, bih_d, bhh_d, xgd, 4*CD, CE);

    enc_rnn_kernel<<<128, 128, ENC_SMEM>>>(Whh_f, Whh_b, xgf, xgb, enc, heb, hdb, cdi);
    dec_rnn_kernel<<<128, 128, DEC_SMEM>>>(Whh_d, xgd, dec, hdb, cdi);

    gemm_tc_kernel<<<dim3(M/BM, CD/BN), 256, GEMM_SMEM>>>(dec, Wq, bq, nullptr, q, CD, CD);
    gemm_tc_kernel<<<dim3(M/BM, CD/BN), 256, GEMM_SMEM>>>(enc, Wk, bk, nullptr, k, CD, CD);
    gemm_tc_kernel<<<dim3(M/BM, CD/BN), 256, GEMM_SMEM>>>(enc, Wv, bv, nullptr, v, CD, CD);

    attn_kernel<<<CB * CTD, 128>>>(eseq, q, k, v, ctx);
    tanh_ln_kernel<<<CB * CTD, 256>>>(dec, ctx, gamma, beta, ln);

    gemm_tc_kernel<<<dim3(M/BM, CV/BN), 256, GEMM_SMEM>>>(ln, Wfc, bfc, nullptr, out, CV, CD);
}

// round 7
// speedup vs baseline: 2.7685x; 1.0897x over previous
#include <cuda_runtime.h>
#include <math.h>
#include <stdint.h>

#define CB   16
#define CTE  128
#define CTD  128
#define CE   512
#define CH   512
#define CD   1024
#define CV   32000

// ---- scratch layout (floats) ----
#define OFF_XE   ((size_t)0)
#define SZ_XE    ((size_t)CB*CTE*CE)
#define OFF_XD   (OFF_XE + SZ_XE)
#define SZ_XD    ((size_t)CB*CTD*CE)
#define OFF_XGF  (OFF_XD + SZ_XD)
#define SZ_XGF   ((size_t)CB*CTE*4*CH)
#define OFF_XGB  (OFF_XGF + SZ_XGF)
#define SZ_XGB   ((size_t)CB*CTE*4*CH)
#define OFF_XGD  (OFF_XGB + SZ_XGB)
#define SZ_XGD   ((size_t)CB*CTD*4*CD)
#define OFF_ENC  (OFF_XGD + SZ_XGD)
#define SZ_ENC   ((size_t)CB*CTE*CD)
#define OFF_DEC  (OFF_ENC + SZ_ENC)
#define SZ_DEC   ((size_t)CB*CTD*CD)
#define OFF_Q    (OFF_DEC + SZ_DEC)
#define SZ_Q     ((size_t)CB*CTD*CD)
#define OFF_K    (OFF_Q + SZ_Q)
#define SZ_K     ((size_t)CB*CTE*CD)
#define OFF_V    (OFF_K + SZ_K)
#define SZ_V     ((size_t)CB*CTE*CD)
#define OFF_CTX  (OFF_V + SZ_V)
#define SZ_CTX   ((size_t)CB*CTD*CD)
#define OFF_LN   (OFF_CTX + SZ_CTX)
#define SZ_LN    ((size_t)CB*CTD*CD)
#define OFF_HE   (OFF_LN + SZ_LN)
#define SZ_HE    ((size_t)2*2*CH*CB)
#define OFF_HD   (OFF_HE + SZ_HE)
#define SZ_HD    ((size_t)2*CD*CB)
#define OFF_CDI  (OFF_HD + SZ_HD)
#define SZ_CDI   ((size_t)CD*CB)
#define SCRATCH_TOTAL (OFF_CDI + SZ_CDI)

__device__ float g_scratch[SCRATCH_TOTAL];
__device__ unsigned g_bar_arrive;
__device__ unsigned g_bar_release;

__device__ __forceinline__ unsigned ld_acq_gpu(const unsigned* p) {
    unsigned v;
    asm volatile("ld.acquire.gpu.global.b32 %0, [%1];" : "=r"(v) : "l"(p) : "memory");
    return v;
}
__device__ __forceinline__ void st_rel_gpu(unsigned* p, unsigned v) {
    asm volatile("st.release.gpu.global.b32 [%0], %1;" :: "l"(p), "r"(v) : "memory");
}

__device__ __forceinline__ void grid_sync_dev(unsigned nb) {
    __syncthreads();
    if (threadIdx.x == 0) {
        __threadfence();
        unsigned gen = ld_acq_gpu(&g_bar_release);
        if (atomicAdd(&g_bar_arrive, 1u) == nb - 1u) {
            g_bar_arrive = 0u;
            st_rel_gpu(&g_bar_release, gen + 1u);
        } else {
            while (ld_acq_gpu(&g_bar_release) == gen) {}
        }
    }
    __syncthreads();
}

__device__ __forceinline__ float sigmoidf_(float x) { return 1.0f / (1.0f + expf(-x)); }

__device__ __forceinline__ uint32_t smem_u32(const void* p) {
    uint32_t a;
    asm("{ .reg .u64 t; cvta.to.shared.u64 t, %1; cvt.u32.u64 %0, t; }" : "=r"(a) : "l"(p));
    return a;
}
__device__ __forceinline__ void cp_async16(uint32_t dst, const void* src) {
    asm volatile("cp.async.cg.shared.global [%0], [%1], 16;" :: "r"(dst), "l"(src));
}
__device__ __forceinline__ void cp_commit() { asm volatile("cp.async.commit_group;" ::: "memory"); }
__device__ __forceinline__ uint32_t f2tf32(float f) {
    uint32_t u;
    asm("cvt.rna.tf32.f32 %0, %1;" : "=r"(u) : "f"(f));
    return u;
}
__device__ __forceinline__ void mma_tf32(float* c, const uint32_t* a, const uint32_t* b) {
    asm volatile(
        "mma.sync.aligned.m16n8k8.row.col.f32.tf32.tf32.f32 "
        "{%0,%1,%2,%3}, {%4,%5,%6,%7}, {%8,%9}, {%0,%1,%2,%3};"
        : "+f"(c[0]), "+f"(c[1]), "+f"(c[2]), "+f"(c[3])
        : "r"(a[0]), "r"(a[1]), "r"(a[2]), "r"(a[3]), "r"(b[0]), "r"(b[1]));
}

// ---- packed f32x2 helpers (Blackwell FFMA2) ----
__device__ __forceinline__ uint64_t pack2(float lo, float hi) {
    uint64_t r;
    asm("mov.b64 %0, {%1,%2};" : "=l"(r) : "f"(lo), "f"(hi));
    return r;
}
__device__ __forceinline__ void unpack2(uint64_t v, float& lo, float& hi) {
    asm("mov.b64 {%0,%1}, %2;" : "=f"(lo), "=f"(hi) : "l"(v));
}
__device__ __forceinline__ void fma2(uint64_t& acc, uint64_t a, uint64_t b) {
    asm("fma.rn.f32x2 %0, %1, %2, %0;" : "+l"(acc) : "l"(a), "l"(b));
}

// ===================== tf32 mma.sync GEMM (unchanged) =====================
#define BM 128
#define BN 128
#define GBK 32
#define GST 3
#define PADK 36
#define TILE_F (128 * PADK)
#define GEMM_SMEM (GST * 2 * TILE_F * 4)

__global__ void __launch_bounds__(256) gemm_tc_kernel(
    const float* __restrict__ A, const float* __restrict__ W,
    const float* __restrict__ bias1, const float* __restrict__ bias2,
    float* __restrict__ C, int N, int K)
{
    extern __shared__ float dsm[];
    float* sA = dsm;
    float* sB = dsm + GST * TILE_F;

    const int tid  = threadIdx.x;
    const int warp = tid >> 5;
    const int lane = tid & 31;
    const int g    = lane >> 2;
    const int tig  = lane & 3;
    const int wm   = warp >> 2;
    const int wn   = warp & 3;
    const int m0   = blockIdx.x * BM;
    const int n0   = blockIdx.y * BN;
    const int nst  = K / GBK;

    const uint32_t sA_u = smem_u32(sA);
    const uint32_t sB_u = smem_u32(sB);

    float acc[4][4][4];
#pragma unroll
    for (int i = 0; i < 4; i++)
#pragma unroll
        for (int j = 0; j < 4; j++)
#pragma unroll
            for (int r = 0; r < 4; r++) acc[i][j][r] = 0.0f;

    auto load_stage = [&](int kidx, int s) {
        const float* Ag = A + (size_t)m0 * K + kidx * GBK;
        const float* Wg = W + (size_t)n0 * K + kidx * GBK;
        uint32_t aBase = sA_u + (uint32_t)(s * TILE_F * 4);
        uint32_t bBase = sB_u + (uint32_t)(s * TILE_F * 4);
#pragma unroll
        for (int q = 0; q < 4; q++) {
            int ch = q * 256 + tid;
            int r = ch >> 3, c = ch & 7;
            cp_async16(aBase + (uint32_t)((r * PADK + c * 4) * 4),
                       Ag + (size_t)r * K + c * 4);
        }
#pragma unroll
        for (int q = 0; q < 4; q++) {
            int ch = q * 256 + tid;
            int r = ch >> 3, c = ch & 7;
            cp_async16(bBase + (uint32_t)((r * PADK + c * 4) * 4),
                       Wg + (size_t)r * K + c * 4);
        }
        cp_commit();
    };

    load_stage(0, 0);
    load_stage(1, 1);

    for (int i = 0; i < nst; i++) {
        if (i + 2 < nst) {
            load_stage(i + 2, (i + 2) % GST);
            asm volatile("cp.async.wait_group 2;" ::: "memory");
        } else if (i + 1 < nst) {
            asm volatile("cp.async.wait_group 1;" ::: "memory");
        } else {
            asm volatile("cp.async.wait_group 0;" ::: "memory");
        }
        __syncthreads();

        const int s = i % GST;
        const float* aS = sA + s * TILE_F;
        const float* bS = sB + s * TILE_F;

#pragma unroll
        for (int ks = 0; ks < 4; ks++) {
            const int kc = ks * 8 + tig;
            uint32_t af[4][4], bf[4][2];
#pragma unroll
            for (int mt = 0; mt < 4; mt++) {
                int row = wm * 64 + mt * 16 + g;
                af[mt][0] = f2tf32(aS[row * PADK + kc]);
                af[mt][1] = f2tf32(aS[(row + 8) * PADK + kc]);
                af[mt][2] = f2tf32(aS[row * PADK + kc + 4]);
                af[mt][3] = f2tf32(aS[(row + 8) * PADK + kc + 4]);
            }
#pragma unroll
            for (int nt = 0; nt < 4; nt++) {
                int n = wn * 32 + nt * 8 + g;
                bf[nt][0] = f2tf32(bS[n * PADK + kc]);
                bf[nt][1] = f2tf32(bS[n * PADK + kc + 4]);
            }
#pragma unroll
            for (int mt = 0; mt < 4; mt++)
#pragma unroll
                for (int nt = 0; nt < 4; nt++)
                    mma_tf32(acc[mt][nt], af[mt], bf[nt]);
        }
        __syncthreads();
    }

#pragma unroll
    for (int nt = 0; nt < 4; nt++) {
        int cn = n0 + wn * 32 + nt * 8 + 2 * tig;
        float b0 = bias1 ? bias1[cn] : 0.0f;
        float b1 = bias1 ? bias1[cn + 1] : 0.0f;
        if (bias2) { b0 += bias2[cn]; b1 += bias2[cn + 1]; }
#pragma unroll
        for (int mt = 0; mt < 4; mt++) {
            int r = m0 + wm * 64 + mt * 16 + g;
            float2 o0 = make_float2(acc[mt][nt][0] + b0, acc[mt][nt][1] + b1);
            float2 o1 = make_float2(acc[mt][nt][2] + b0, acc[mt][nt][3] + b1);
            *(float2*)(C + (size_t)r * N + cn) = o0;
            *(float2*)(C + (size_t)(r + 8) * N + cn) = o1;
        }
    }
}

// ---- embedding gather ----
__global__ void __launch_bounds__(128) embed_kernel(
    const int* __restrict__ eseq, const int* __restrict__ dseq,
    const float* __restrict__ eemb, const float* __restrict__ demb,
    float* __restrict__ xe, float* __restrict__ xd)
{
    int r = blockIdx.x;
    if (r < CB * CTE) {
        int tok = eseq[r];
        ((float4*)(xe + (size_t)r * CE))[threadIdx.x] =
            ((const float4*)(eemb + (size_t)tok * CE))[threadIdx.x];
    } else {
        int r2 = r - CB * CTE;
        int tok = dseq[r2];
        ((float4*)(xd + (size_t)r2 * CE))[threadIdx.x] =
            ((const float4*)(demb + (size_t)tok * CE))[threadIdx.x];
    }
}

// ===================== encoder recurrence (f32x2) =====================
// weights gate-interleaved in smem: [ul][k][4]=(wi,wf,wg,wo); h staged [b][k].
#define EW_STRIDE (4 * CH + 4)          // 2052 floats per ul
#define HPAD_E    (CH + 4)              // 516
#define ENC_SMEM ((8 * EW_STRIDE + CB * HPAD_E) * 4)

__global__ void __launch_bounds__(128) enc_rnn_kernel(
    const float* __restrict__ Whh_f, const float* __restrict__ Whh_b,
    const float* __restrict__ xgf, const float* __restrict__ xgb,
    float* __restrict__ enc, float* __restrict__ hebuf,   // [buf][dir][b][CH]
    float* __restrict__ hd0, float* __restrict__ cdi)     // [b][CD]
{
    extern __shared__ float sm[];
    float* wsm = sm;
    float* hsm = sm + 8 * EW_STRIDE;

    const int tid = threadIdx.x;
    const int b = tid & 15, ul = tid >> 4;
    const int dir = blockIdx.x >> 6;
    const int u = (blockIdx.x & 63) * 8 + ul;
    const int ubase = (blockIdx.x & 63) * 8;

    const float* Whh = dir ? Whh_b : Whh_f;
    const float* xg  = dir ? xgb : xgf;

    // one-time weight load + gate-interleave transpose: 4096 float4
    for (int i = tid; i < 4096; i += 128) {
        int ulw = i >> 9;
        int g = (i >> 7) & 3;
        int k4 = i & 127;
        float4 v = *(const float4*)(Whh + ((size_t)(g * CH + ubase + ulw)) * CH + k4 * 4);
        float* dst = wsm + ulw * EW_STRIDE + (k4 * 4) * 4 + g;
        dst[0] = v.x; dst[4] = v.y; dst[8] = v.z; dst[12] = v.w;
    }

    const ulonglong2* wrow = (const ulonglong2*)(wsm + ul * EW_STRIDE);
    const float* hrow = hsm + b * HPAD_E;

    float c = 0.0f, h = 0.0f;
    __stcg(&hebuf[((size_t)(0 * 2 + dir) * CB + b) * CH + u], 0.0f);
    grid_sync_dev(gridDim.x);

    for (int t = 0; t < CTE; t++) {
        const int cur = t & 1;
        {
            const float4* src = (const float4*)(hebuf + (size_t)(cur * 2 + dir) * (CB * CH));
            for (int i = tid; i < CB * CH / 4; i += 128) {
                int bb = i >> 7, k4 = i & 127;
                *(float4*)(hsm + bb * HPAD_E + k4 * 4) = __ldcg(&src[i]);
            }
        }
        __syncthreads();

        const int te = dir ? (CTE - 1 - t) : t;
        size_t xb = ((size_t)(b * CTE + te)) * (4 * CH) + u;
        uint64_t a_if = pack2(xg[xb], xg[xb + CH]);
        uint64_t a_go = pack2(xg[xb + 2 * CH], xg[xb + 3 * CH]);

#pragma unroll 2
        for (int k4 = 0; k4 < CH / 4; k4++) {
            float4 h4 = *(const float4*)(hrow + k4 * 4);
#pragma unroll
            for (int j = 0; j < 4; j++) {
                ulonglong2 wv = wrow[k4 * 4 + j];
                float hj = (j == 0) ? h4.x : (j == 1) ? h4.y : (j == 2) ? h4.z : h4.w;
                uint64_t hh = pack2(hj, hj);
                fma2(a_if, wv.x, hh);
                fma2(a_go, wv.y, hh);
            }
        }

        float ai, af, ag, ao;
        unpack2(a_if, ai, af);
        unpack2(a_go, ag, ao);
        float ig = sigmoidf_(ai), fg = sigmoidf_(af);
        float gg = tanhf(ag),     og = sigmoidf_(ao);
        c = fg * c + ig * gg;
        h = og * tanhf(c);

        __stcg(&hebuf[((size_t)((cur ^ 1) * 2 + dir) * CB + b) * CH + u], h);
        enc[((size_t)(b * CTE + te)) * CD + dir * CH + u] = h;
        grid_sync_dev(gridDim.x);
    }

    __stcg(&hd0[(size_t)b * CD + dir * CH + u], h);
    __stcg(&cdi[(size_t)b * CD + dir * CH + u], c);
}

// ===================== decoder recurrence (f32x2) =====================
#define DW_STRIDE (4 * CD + 4)          // 4100 floats per ul
#define HPAD_D    (CD + 4)              // 1028
#define DEC_SMEM ((8 * DW_STRIDE + CB * HPAD_D) * 4)   // 196992 B

__global__ void __launch_bounds__(128) dec_rnn_kernel(
    const float* __restrict__ Whh, const float* __restrict__ xg,
    float* __restrict__ dec, float* __restrict__ hbuf,   // [buf][b][CD]
    const float* __restrict__ cinit)                     // [b][CD]
{
    extern __shared__ float sm[];
    float* wsm = sm;
    float* hsm = sm + 8 * DW_STRIDE;

    const int tid = threadIdx.x;
    const int b = tid & 15, ul = tid >> 4;
    const int u = blockIdx.x * 8 + ul;
    const int ubase = blockIdx.x * 8;

    // one-time weight load + gate-interleave transpose: 8192 float4
    for (int i = tid; i < 8192; i += 128) {
        int ulw = i >> 10;
        int g = (i >> 8) & 3;
        int k4 = i & 255;
        float4 v = *(const float4*)(Whh + ((size_t)(g * CD + ubase + ulw)) * CD + k4 * 4);
        float* dst = wsm + ulw * DW_STRIDE + (k4 * 4) * 4 + g;
        dst[0] = v.x; dst[4] = v.y; dst[8] = v.z; dst[12] = v.w;
    }

    const ulonglong2* wrow = (const ulonglong2*)(wsm + ul * DW_STRIDE);
    const float* hrow = hsm + b * HPAD_D;

    float c = __ldcg(&cinit[(size_t)b * CD + u]);

    for (int t = 0; t < CTD; t++) {
        const int cur = t & 1;
        {
            const float4* src = (const float4*)(hbuf + (size_t)cur * (CB * CD));
            for (int i = tid; i < CB * CD / 4; i += 128) {
                int bb = i >> 8, k4 = i & 255;
                *(float4*)(hsm + bb * HPAD_D + k4 * 4) = __ldcg(&src[i]);
            }
        }
        __syncthreads();

        size_t xb = ((size_t)(b * CTD + t)) * (4 * CD) + u;
        uint64_t a_if = pack2(xg[xb], xg[xb + CD]);
        uint64_t a_go = pack2(xg[xb + 2 * CD], xg[xb + 3 * CD]);

#pragma unroll 2
        for (int k4 = 0; k4 < CD / 4; k4++) {
            float4 h4 = *(const float4*)(hrow + k4 * 4);
#pragma unroll
            for (int j = 0; j < 4; j++) {
                ulonglong2 wv = wrow[k4 * 4 + j];
                float hj = (j == 0) ? h4.x : (j == 1) ? h4.y : (j == 2) ? h4.z : h4.w;
                uint64_t hh = pack2(hj, hj);
                fma2(a_if, wv.x, hh);
                fma2(a_go, wv.y, hh);
            }
        }

        float ai, af, ag, ao;
        unpack2(a_if, ai, af);
        unpack2(a_go, ag, ao);
        float ig = sigmoidf_(ai), fg = sigmoidf_(af);
        float gg = tanhf(ag),     og = sigmoidf_(ao);
        c = fg * c + ig * gg;
        float h = og * tanhf(c);

        __stcg(&hbuf[(size_t)(cur ^ 1) * (CB * CD) + (size_t)b * CD + u], h);
        dec[((size_t)(b * CTD + t)) * CD + u] = h;
        grid_sync_dev(gridDim.x);
    }
}

// ---- fused attention: one block per (b, qt) ----
__global__ void __launch_bounds__(128) attn_kernel(
    const int* __restrict__ eseq,
    const float* __restrict__ q, const float* __restrict__ k,
    const float* __restrict__ v, float* __restrict__ ctx)
{
    __shared__ float qs[CD];
    __shared__ float att[CTE];
    __shared__ float red[128];
    const int tid = threadIdx.x;
    const int b = blockIdx.x >> 7, qt = blockIdx.x & 127;
    const size_t qrow = (size_t)(b * CTD + qt) * CD;

    ((float4*)qs)[tid]       = ((const float4*)(q + qrow))[tid];
    ((float4*)qs)[tid + 128] = ((const float4*)(q + qrow))[tid + 128];
    __syncthreads();

    const float4* kr = (const float4*)(k + (size_t)(b * CTE + tid) * CD);
    float s = 0.0f;
#pragma unroll 8
    for (int k4 = 0; k4 < CD / 4; k4++) {
        float4 kv = kr[k4];
        s = fmaf(qs[k4*4+0], kv.x, s); s = fmaf(qs[k4*4+1], kv.y, s);
        s = fmaf(qs[k4*4+2], kv.z, s); s = fmaf(qs[k4*4+3], kv.w, s);
    }
    s *= 0.03125f;
    if (eseq[b * CTE + tid] == 0) s = -1e30f;

    red[tid] = s; __syncthreads();
#pragma unroll
    for (int o = 64; o > 0; o >>= 1) {
        if (tid < o) red[tid] = fmaxf(red[tid], red[tid + o]);
        __syncthreads();
    }
    float mx = red[0]; __syncthreads();
    float e = expf(s - mx);
    red[tid] = e; __syncthreads();
#pragma unroll
    for (int o = 64; o > 0; o >>= 1) {
        if (tid < o) red[tid] += red[tid + o];
        __syncthreads();
    }
    att[tid] = e / red[0];
    __syncthreads();

    float acc[8] = {0,0,0,0,0,0,0,0};
    for (int kt = 0; kt < CTE; kt++) {
        float a = att[kt];
        const float* vr = v + (size_t)(b * CTE + kt) * CD;
#pragma unroll
        for (int j = 0; j < 8; j++) acc[j] = fmaf(a, vr[tid + j * 128], acc[j]);
    }
    float* cr = ctx + (size_t)(b * CTD + qt) * CD;
#pragma unroll
    for (int j = 0; j < 8; j++) cr[tid + j * 128] = acc[j];
}

// ---- tanh(dec + ctx) -> layernorm ----
__global__ void __launch_bounds__(256) tanh_ln_kernel(
    const float* __restrict__ dec, const float* __restrict__ ctx,
    const float* __restrict__ gamma, const float* __restrict__ beta,
    float* __restrict__ ln)
{
    __shared__ float rs[8], rss[8];
    const int tid = threadIdx.x;
    const int row = blockIdx.x;
    const float4 a = ((const float4*)(dec + (size_t)row * CD))[tid];
    const float4 b = ((const float4*)(ctx + (size_t)row * CD))[tid];
    float t0 = tanhf(a.x + b.x), t1 = tanhf(a.y + b.y);
    float t2 = tanhf(a.z + b.z), t3 = tanhf(a.w + b.w);
    float s = t0 + t1 + t2 + t3;
    float ss = t0*t0 + t1*t1 + t2*t2 + t3*t3;
#pragma unroll
    for (int o = 16; o > 0; o >>= 1) {
        s  += __shfl_xor_sync(0xffffffffu, s, o);
        ss += __shfl_xor_sync(0xffffffffu, ss, o);
    }
    if ((tid & 31) == 0) { rs[tid >> 5] = s; rss[tid >> 5] = ss; }
    __syncthreads();
    if (tid < 8) { s = rs[tid]; ss = rss[tid]; }
    else { s = 0; ss = 0; }
    if (tid < 32) {
#pragma unroll
        for (int o = 4; o > 0; o >>= 1) {
            s  += __shfl_xor_sync(0xffffffffu, s, o);
            ss += __shfl_xor_sync(0xffffffffu, ss, o);
        }
        if (tid == 0) { rs[0] = s; rss[0] = ss; }
    }
    __syncthreads();
    float mu = rs[0] * (1.0f / CD);
    float var = rss[0] * (1.0f / CD) - mu * mu;
    float rstd = rsqrtf(var + 1e-5f);
    const float4 g = ((const float4*)gamma)[tid];
    const float4 be = ((const float4*)beta)[tid];
    float4 o;
    o.x = (t0 - mu) * rstd * g.x + be.x;
    o.y = (t1 - mu) * rstd * g.y + be.y;
    o.z = (t2 - mu) * rstd * g.z + be.z;
    o.w = (t3 - mu) * rstd * g.w + be.w;
    ((float4*)(ln + (size_t)row * CD))[tid] = o;
}

extern "C" void kernel_launch(void* const* d_in, const int* in_sizes, int n_in,
                              void* d_out, int out_size) {
    const int*   eseq  = (const int*)d_in[0];
    const int*   dseq  = (const int*)d_in[1];
    const float* eemb  = (const float*)d_in[2];
    const float* demb  = (const float*)d_in[3];
    const float* Wih_f = (const float*)d_in[4];
    const float* Whh_f = (const float*)d_in[5];
    const float* bih_f = (const float*)d_in[6];
    const float* bhh_f = (const float*)d_in[7];
    const float* Wih_b = (const float*)d_in[8];
    const float* Whh_b = (const float*)d_in[9];
    const float* bih_b = (const float*)d_in[10];
    const float* bhh_b = (const float*)d_in[11];
    const float* Wih_d = (const float*)d_in[12];
    const float* Whh_d = (const float*)d_in[13];
    const float* bih_d = (const float*)d_in[14];
    const float* bhh_d = (const float*)d_in[15];
    const float* Wq = (const float*)d_in[16];
    const float* bq = (const float*)d_in[17];
    const float* Wk = (const float*)d_in[18];
    const float* bk = (const float*)d_in[19];
    const float* Wv = (const float*)d_in[20];
    const float* bv = (const float*)d_in[21];
    const float* Wfc = (const float*)d_in[22];
    const float* bfc = (const float*)d_in[23];
    const float* gamma = (const float*)d_in[24];
    const float* beta  = (const float*)d_in[25];
    float* out = (float*)d_out;

    float* S = nullptr;
    cudaGetSymbolAddress((void**)&S, g_scratch);
    float* xe  = S + OFF_XE;
    float* xd  = S + OFF_XD;
    float* xgf = S + OFF_XGF;
    float* xgb = S + OFF_XGB;
    float* xgd = S + OFF_XGD;
    float* enc = S + OFF_ENC;
    float* dec = S + OFF_DEC;
    float* q   = S + OFF_Q;
    float* k   = S + OFF_K;
    float* v   = S + OFF_V;
    float* ctx = S + OFF_CTX;
    float* ln  = S + OFF_LN;
    float* heb = S + OFF_HE;
    float* hdb = S + OFF_HD;
    float* cdi = S + OFF_CDI;

    cudaFuncSetAttribute(enc_rnn_kernel,
                         cudaFuncAttributeMaxDynamicSharedMemorySize, ENC_SMEM);
    cudaFuncSetAttribute(dec_rnn_kernel,
                         cudaFuncAttributeMaxDynamicSharedMemorySize, DEC_SMEM);
    cudaFuncSetAttribute(gemm_tc_kernel,
                         cudaFuncAttributeMaxDynamicSharedMemorySize, GEMM_SMEM);

    const int M = CB * CTE;  // 2048 (== CB*CTD)

    embed_kernel<<<CB * CTE + CB * CTD, 128>>>(eseq, dseq, eemb, demb, xe, xd);

    gemm_tc_kernel<<<dim3(M/BM, 4*CH/BN), 256, GEMM_SMEM>>>(xe, Wih_f, bih_f, bhh_f, xgf, 4*CH, CE);
    gemm_tc_kernel<<<dim3(M/BM, 4*CH/BN), 256, GEMM_SMEM>>>(xe, Wih_b, bih_b, bhh_b, xgb, 4*CH, CE);
    gemm_tc_kernel<<<dim3(M/BM, 4*CD/BN), 256, GEMM_SMEM>>>(xd, Wih_d, bih_d, bhh_d, xgd, 4*CD, CE);

    enc_rnn_kernel<<<128, 128, ENC_SMEM>>>(Whh_f, Whh_b, xgf, xgb, enc, heb, hdb, cdi);
    dec_rnn_kernel<<<128, 128, DEC_SMEM>>>(Whh_d, xgd, dec, hdb, cdi);

    gemm_tc_kernel<<<dim3(M/BM, CD/BN), 256, GEMM_SMEM>>>(dec, Wq, bq, nullptr, q, CD, CD);
    gemm_tc_kernel<<<dim3(M/BM, CD/BN), 256, GEMM_SMEM>>>(enc, Wk, bk, nullptr, k, CD, CD);
    gemm_tc_kernel<<<dim3(M/BM, CD/BN), 256, GEMM_SMEM>>>(enc, Wv, bv, nullptr, v, CD, CD);

    attn_kernel<<<CB * CTD, 128>>>(eseq, q, k, v, ctx);
    tanh_ln_kernel<<<CB * CTD, 256>>>(dec, ctx, gamma, beta, ln);

    gemm_tc_kernel<<<dim3(M/BM, CV/BN), 256, GEMM_SMEM>>>(ln, Wfc, bfc, nullptr, out, CV, CD);
}

// round 8
// speedup vs baseline: 3.8948x; 1.4068x over previous
#include <cuda_runtime.h>
#include <math.h>
#include <stdint.h>

#define CB   16
#define CTE  128
#define CTD  128
#define CE   512
#define CH   512
#define CD   1024
#define CV   32000

// ---- scratch layout (floats) ----
#define OFF_XE   ((size_t)0)
#define SZ_XE    ((size_t)CB*CTE*CE)
#define OFF_XD   (OFF_XE + SZ_XE)
#define SZ_XD    ((size_t)CB*CTD*CE)
#define OFF_XGF  (OFF_XD + SZ_XD)
#define SZ_XGF   ((size_t)CB*CTE*4*CH)
#define OFF_XGB  (OFF_XGF + SZ_XGF)
#define SZ_XGB   ((size_t)CB*CTE*4*CH)
#define OFF_XGD  (OFF_XGB + SZ_XGB)
#define SZ_XGD   ((size_t)CB*CTD*4*CD)
#define OFF_ENC  (OFF_XGD + SZ_XGD)
#define SZ_ENC   ((size_t)CB*CTE*CD)
#define OFF_DEC  (OFF_ENC + SZ_ENC)
#define SZ_DEC   ((size_t)CB*CTD*CD)
#define OFF_Q    (OFF_DEC + SZ_DEC)
#define SZ_Q     ((size_t)CB*CTD*CD)
#define OFF_K    (OFF_Q + SZ_Q)
#define SZ_K     ((size_t)CB*CTE*CD)
#define OFF_V    (OFF_K + SZ_K)
#define SZ_V     ((size_t)CB*CTE*CD)
#define OFF_CTX  (OFF_V + SZ_V)
#define SZ_CTX   ((size_t)CB*CTD*CD)
#define OFF_LN   (OFF_CTX + SZ_CTX)
#define SZ_LN    ((size_t)CB*CTD*CD)
#define OFF_HE   (OFF_LN + SZ_LN)
#define SZ_HE    ((size_t)2*2*CH*CB)
#define OFF_HD   (OFF_HE + SZ_HE)
#define SZ_HD    ((size_t)2*CD*CB)
#define OFF_CDI  (OFF_HD + SZ_HD)
#define SZ_CDI   ((size_t)CD*CB)
#define SCRATCH_TOTAL (OFF_CDI + SZ_CDI)

__device__ float g_scratch[SCRATCH_TOTAL];
__device__ unsigned g_bar_arrive;
__device__ unsigned g_bar_release;

__device__ __forceinline__ unsigned ld_acq_gpu(const unsigned* p) {
    unsigned v;
    asm volatile("ld.acquire.gpu.global.b32 %0, [%1];" : "=r"(v) : "l"(p) : "memory");
    return v;
}
__device__ __forceinline__ void st_rel_gpu(unsigned* p, unsigned v) {
    asm volatile("st.release.gpu.global.b32 [%0], %1;" :: "l"(p), "r"(v) : "memory");
}

__device__ __forceinline__ void grid_sync_dev(unsigned nb) {
    __syncthreads();
    if (threadIdx.x == 0) {
        __threadfence();
        unsigned gen = ld_acq_gpu(&g_bar_release);
        if (atomicAdd(&g_bar_arrive, 1u) == nb - 1u) {
            g_bar_arrive = 0u;
            st_rel_gpu(&g_bar_release, gen + 1u);
        } else {
            while (ld_acq_gpu(&g_bar_release) == gen) {}
        }
    }
    __syncthreads();
}

__device__ __forceinline__ float sigmoidf_(float x) { return 1.0f / (1.0f + expf(-x)); }

__device__ __forceinline__ uint32_t smem_u32(const void* p) {
    uint32_t a;
    asm("{ .reg .u64 t; cvta.to.shared.u64 t, %1; cvt.u32.u64 %0, t; }" : "=r"(a) : "l"(p));
    return a;
}
__device__ __forceinline__ void cp_async16(uint32_t dst, const void* src) {
    asm volatile("cp.async.cg.shared.global [%0], [%1], 16;" :: "r"(dst), "l"(src));
}
__device__ __forceinline__ void cp_commit() { asm volatile("cp.async.commit_group;" ::: "memory"); }
__device__ __forceinline__ uint32_t f2tf32(float f) {
    uint32_t u;
    asm("cvt.rna.tf32.f32 %0, %1;" : "=r"(u) : "f"(f));
    return u;
}
__device__ __forceinline__ void mma_tf32(float* c, const uint32_t* a, const uint32_t* b) {
    asm volatile(
        "mma.sync.aligned.m16n8k8.row.col.f32.tf32.tf32.f32 "
        "{%0,%1,%2,%3}, {%4,%5,%6,%7}, {%8,%9}, {%0,%1,%2,%3};"
        : "+f"(c[0]), "+f"(c[1]), "+f"(c[2]), "+f"(c[3])
        : "r"(a[0]), "r"(a[1]), "r"(a[2]), "r"(a[3]), "r"(b[0]), "r"(b[1]));
}

// ---- packed f32x2 helpers ----
__device__ __forceinline__ uint64_t pack2(float lo, float hi) {
    uint64_t r;
    asm("mov.b64 %0, {%1,%2};" : "=l"(r) : "f"(lo), "f"(hi));
    return r;
}
__device__ __forceinline__ void unpack2(uint64_t v, float& lo, float& hi) {
    asm("mov.b64 {%0,%1}, %2;" : "=f"(lo), "=f"(hi) : "l"(v));
}
__device__ __forceinline__ void fma2(uint64_t& acc, uint64_t a, uint64_t b) {
    asm("fma.rn.f32x2 %0, %1, %2, %0;" : "+l"(acc) : "l"(a), "l"(b));
}
__device__ __forceinline__ void add2(uint64_t& a, uint64_t b) {
    asm("add.rn.f32x2 %0, %0, %1;" : "+l"(a) : "l"(b));
}

// ===================== tf32 mma.sync GEMM (unchanged) =====================
#define BM 128
#define BN 128
#define GBK 32
#define GST 3
#define PADK 36
#define TILE_F (128 * PADK)
#define GEMM_SMEM (GST * 2 * TILE_F * 4)

__global__ void __launch_bounds__(256) gemm_tc_kernel(
    const float* __restrict__ A, const float* __restrict__ W,
    const float* __restrict__ bias1, const float* __restrict__ bias2,
    float* __restrict__ C, int N, int K)
{
    extern __shared__ float dsm[];
    float* sA = dsm;
    float* sB = dsm + GST * TILE_F;

    const int tid  = threadIdx.x;
    const int warp = tid >> 5;
    const int lane = tid & 31;
    const int g    = lane >> 2;
    const int tig  = lane & 3;
    const int wm   = warp >> 2;
    const int wn   = warp & 3;
    const int m0   = blockIdx.x * BM;
    const int n0   = blockIdx.y * BN;
    const int nst  = K / GBK;

    const uint32_t sA_u = smem_u32(sA);
    const uint32_t sB_u = smem_u32(sB);

    float acc[4][4][4];
#pragma unroll
    for (int i = 0; i < 4; i++)
#pragma unroll
        for (int j = 0; j < 4; j++)
#pragma unroll
            for (int r = 0; r < 4; r++) acc[i][j][r] = 0.0f;

    auto load_stage = [&](int kidx, int s) {
        const float* Ag = A + (size_t)m0 * K + kidx * GBK;
        const float* Wg = W + (size_t)n0 * K + kidx * GBK;
        uint32_t aBase = sA_u + (uint32_t)(s * TILE_F * 4);
        uint32_t bBase = sB_u + (uint32_t)(s * TILE_F * 4);
#pragma unroll
        for (int q = 0; q < 4; q++) {
            int ch = q * 256 + tid;
            int r = ch >> 3, c = ch & 7;
            cp_async16(aBase + (uint32_t)((r * PADK + c * 4) * 4),
                       Ag + (size_t)r * K + c * 4);
        }
#pragma unroll
        for (int q = 0; q < 4; q++) {
            int ch = q * 256 + tid;
            int r = ch >> 3, c = ch & 7;
            cp_async16(bBase + (uint32_t)((r * PADK + c * 4) * 4),
                       Wg + (size_t)r * K + c * 4);
        }
        cp_commit();
    };

    load_stage(0, 0);
    load_stage(1, 1);

    for (int i = 0; i < nst; i++) {
        if (i + 2 < nst) {
            load_stage(i + 2, (i + 2) % GST);
            asm volatile("cp.async.wait_group 2;" ::: "memory");
        } else if (i + 1 < nst) {
            asm volatile("cp.async.wait_group 1;" ::: "memory");
        } else {
            asm volatile("cp.async.wait_group 0;" ::: "memory");
        }
        __syncthreads();

        const int s = i % GST;
        const float* aS = sA + s * TILE_F;
        const float* bS = sB + s * TILE_F;

#pragma unroll
        for (int ks = 0; ks < 4; ks++) {
            const int kc = ks * 8 + tig;
            uint32_t af[4][4], bf[4][2];
#pragma unroll
            for (int mt = 0; mt < 4; mt++) {
                int row = wm * 64 + mt * 16 + g;
                af[mt][0] = f2tf32(aS[row * PADK + kc]);
                af[mt][1] = f2tf32(aS[(row + 8) * PADK + kc]);
                af[mt][2] = f2tf32(aS[row * PADK + kc + 4]);
                af[mt][3] = f2tf32(aS[(row + 8) * PADK + kc + 4]);
            }
#pragma unroll
            for (int nt = 0; nt < 4; nt++) {
                int n = wn * 32 + nt * 8 + g;
                bf[nt][0] = f2tf32(bS[n * PADK + kc]);
                bf[nt][1] = f2tf32(bS[n * PADK + kc + 4]);
            }
#pragma unroll
            for (int mt = 0; mt < 4; mt++)
#pragma unroll
                for (int nt = 0; nt < 4; nt++)
                    mma_tf32(acc[mt][nt], af[mt], bf[nt]);
        }
        __syncthreads();
    }

#pragma unroll
    for (int nt = 0; nt < 4; nt++) {
        int cn = n0 + wn * 32 + nt * 8 + 2 * tig;
        float b0 = bias1 ? bias1[cn] : 0.0f;
        float b1 = bias1 ? bias1[cn + 1] : 0.0f;
        if (bias2) { b0 += bias2[cn]; b1 += bias2[cn + 1]; }
#pragma unroll
        for (int mt = 0; mt < 4; mt++) {
            int r = m0 + wm * 64 + mt * 16 + g;
            float2 o0 = make_float2(acc[mt][nt][0] + b0, acc[mt][nt][1] + b1);
            float2 o1 = make_float2(acc[mt][nt][2] + b0, acc[mt][nt][3] + b1);
            *(float2*)(C + (size_t)r * N + cn) = o0;
            *(float2*)(C + (size_t)(r + 8) * N + cn) = o1;
        }
    }
}

// ---- embedding gather ----
__global__ void __launch_bounds__(128) embed_kernel(
    const int* __restrict__ eseq, const int* __restrict__ dseq,
    const float* __restrict__ eemb, const float* __restrict__ demb,
    float* __restrict__ xe, float* __restrict__ xd)
{
    int r = blockIdx.x;
    if (r < CB * CTE) {
        int tok = eseq[r];
        ((float4*)(xe + (size_t)r * CE))[threadIdx.x] =
            ((const float4*)(eemb + (size_t)tok * CE))[threadIdx.x];
    } else {
        int r2 = r - CB * CTE;
        int tok = dseq[r2];
        ((float4*)(xd + (size_t)r2 * CE))[threadIdx.x] =
            ((const float4*)(demb + (size_t)tok * CE))[threadIdx.x];
    }
}

// ===================== encoder recurrence (512 thr, k-quartered) =====================
#define EW_STRIDE (4 * CH + 4)          // 2052 floats
#define HPAD_E    (CH + 4)              // 516
#define ENC_RED_F (8 * EW_STRIDE + CB * HPAD_E)
#define ENC_SMEM  (ENC_RED_F * 4 + 3 * 8 * 16 * 16)

__global__ void __launch_bounds__(512) enc_rnn_kernel(
    const float* __restrict__ Whh_f, const float* __restrict__ Whh_b,
    const float* __restrict__ xgf, const float* __restrict__ xgb,
    float* __restrict__ enc, float* __restrict__ hebuf,   // [buf][dir][b][CH]
    float* __restrict__ hd0, float* __restrict__ cdi)     // [b][CD]
{
    extern __shared__ float sm[];
    float* wsm = sm;
    float* hsm = sm + 8 * EW_STRIDE;
    ulonglong2* red = (ulonglong2*)(sm + ENC_RED_F);      // [3][8][16]

    const int tid = threadIdx.x;
    const int b = tid & 15, ul = (tid >> 4) & 7, qr = tid >> 7;
    const int dir = blockIdx.x >> 6;
    const int u = (blockIdx.x & 63) * 8 + ul;
    const int ubase = (blockIdx.x & 63) * 8;

    const float* Whh = dir ? Whh_b : Whh_f;
    const float* xg  = dir ? xgb : xgf;

    // one-time weight load + gate-interleave: 4096 float4
    for (int i = tid; i < 4096; i += 512) {
        int ulw = i >> 9;
        int g = (i >> 7) & 3;
        int k4 = i & 127;
        float4 v = *(const float4*)(Whh + ((size_t)(g * CH + ubase + ulw)) * CH + k4 * 4);
        float* dst = wsm + ulw * EW_STRIDE + (k4 * 4) * 4 + g;
        dst[0] = v.x; dst[4] = v.y; dst[8] = v.z; dst[12] = v.w;
    }

    const ulonglong2* wrow = (const ulonglong2*)(wsm + ul * EW_STRIDE) + qr * 128;
    const float* hrow = hsm + b * HPAD_E + qr * 128;

    float c = 0.0f, h = 0.0f;
    if (qr == 0)
        __stcg(&hebuf[((size_t)(0 * 2 + dir) * CB + b) * CH + u], 0.0f);
    grid_sync_dev(gridDim.x);

    for (int t = 0; t < CTE; t++) {
        const int cur = t & 1;
        {
            const float4* src = (const float4*)(hebuf + (size_t)(cur * 2 + dir) * (CB * CH));
            for (int i = tid; i < CB * CH / 4; i += 512) {
                int bb = i >> 7, k4 = i & 127;
                *(float4*)(hsm + bb * HPAD_E + k4 * 4) = __ldcg(&src[i]);
            }
        }
        __syncthreads();

        const int te = dir ? (CTE - 1 - t) : t;
        uint64_t a_if = 0, a_go = 0;
        if (qr == 0) {
            size_t xb = ((size_t)(b * CTE + te)) * (4 * CH) + u;
            a_if = pack2(xg[xb], xg[xb + CH]);
            a_go = pack2(xg[xb + 2 * CH], xg[xb + 3 * CH]);
        }

#pragma unroll 4
        for (int k4 = 0; k4 < 32; k4++) {
            float4 h4 = *(const float4*)(hrow + k4 * 4);
#pragma unroll
            for (int j = 0; j < 4; j++) {
                ulonglong2 wv = wrow[k4 * 4 + j];
                float hj = (j == 0) ? h4.x : (j == 1) ? h4.y : (j == 2) ? h4.z : h4.w;
                uint64_t hh = pack2(hj, hj);
                fma2(a_if, wv.x, hh);
                fma2(a_go, wv.y, hh);
            }
        }

        if (qr) {
            ulonglong2 r; r.x = a_if; r.y = a_go;
            red[((qr - 1) * 8 + ul) * 16 + b] = r;
        }
        __syncthreads();
        if (qr == 0) {
#pragma unroll
            for (int q = 0; q < 3; q++) {
                ulonglong2 r = red[(q * 8 + ul) * 16 + b];
                add2(a_if, r.x);
                add2(a_go, r.y);
            }
            float ai, af, ag, ao;
            unpack2(a_if, ai, af);
            unpack2(a_go, ag, ao);
            float ig = sigmoidf_(ai), fg = sigmoidf_(af);
            float gg = tanhf(ag),     og = sigmoidf_(ao);
            c = fg * c + ig * gg;
            h = og * tanhf(c);

            __stcg(&hebuf[((size_t)((cur ^ 1) * 2 + dir) * CB + b) * CH + u], h);
            enc[((size_t)(b * CTE + te)) * CD + dir * CH + u] = h;
        }
        grid_sync_dev(gridDim.x);
    }

    if (qr == 0) {
        __stcg(&hd0[(size_t)b * CD + dir * CH + u], h);
        __stcg(&cdi[(size_t)b * CD + dir * CH + u], c);
    }
}

// ===================== decoder recurrence (512 thr, k-quartered) =====================
#define DW_STRIDE (4 * CD + 4)          // 4100 floats
#define HPAD_D    (CD + 4)              // 1028
#define DEC_RED_F (8 * DW_STRIDE + CB * HPAD_D)
#define DEC_SMEM  (DEC_RED_F * 4 + 3 * 8 * 16 * 16)

__global__ void __launch_bounds__(512) dec_rnn_kernel(
    const float* __restrict__ Whh, const float* __restrict__ xg,
    float* __restrict__ dec, float* __restrict__ hbuf,   // [buf][b][CD]
    const float* __restrict__ cinit)                     // [b][CD]
{
    extern __shared__ float sm[];
    float* wsm = sm;
    float* hsm = sm + 8 * DW_STRIDE;
    ulonglong2* red = (ulonglong2*)(sm + DEC_RED_F);     // [3][8][16]

    const int tid = threadIdx.x;
    const int b = tid & 15, ul = (tid >> 4) & 7, qr = tid >> 7;
    const int u = blockIdx.x * 8 + ul;
    const int ubase = blockIdx.x * 8;

    // one-time weight load + gate-interleave: 8192 float4
    for (int i = tid; i < 8192; i += 512) {
        int ulw = i >> 10;
        int g = (i >> 8) & 3;
        int k4 = i & 255;
        float4 v = *(const float4*)(Whh + ((size_t)(g * CD + ubase + ulw)) * CD + k4 * 4);
        float* dst = wsm + ulw * DW_STRIDE + (k4 * 4) * 4 + g;
        dst[0] = v.x; dst[4] = v.y; dst[8] = v.z; dst[12] = v.w;
    }

    const ulonglong2* wrow = (const ulonglong2*)(wsm + ul * DW_STRIDE) + qr * 256;
    const float* hrow = hsm + b * HPAD_D + qr * 256;

    float c = (qr == 0) ? __ldcg(&cinit[(size_t)b * CD + u]) : 0.0f;

    for (int t = 0; t < CTD; t++) {
        const int cur = t & 1;
        {
            const float4* src = (const float4*)(hbuf + (size_t)cur * (CB * CD));
            for (int i = tid; i < CB * CD / 4; i += 512) {
                int bb = i >> 8, k4 = i & 255;
                *(float4*)(hsm + bb * HPAD_D + k4 * 4) = __ldcg(&src[i]);
            }
        }
        __syncthreads();

        uint64_t a_if = 0, a_go = 0;
        if (qr == 0) {
            size_t xb = ((size_t)(b * CTD + t)) * (4 * CD) + u;
            a_if = pack2(xg[xb], xg[xb + CD]);
            a_go = pack2(xg[xb + 2 * CD], xg[xb + 3 * CD]);
        }

#pragma unroll 4
        for (int k4 = 0; k4 < 64; k4++) {
            float4 h4 = *(const float4*)(hrow + k4 * 4);
#pragma unroll
            for (int j = 0; j < 4; j++) {
                ulonglong2 wv = wrow[k4 * 4 + j];
                float hj = (j == 0) ? h4.x : (j == 1) ? h4.y : (j == 2) ? h4.z : h4.w;
                uint64_t hh = pack2(hj, hj);
                fma2(a_if, wv.x, hh);
                fma2(a_go, wv.y, hh);
            }
        }

        if (qr) {
            ulonglong2 r; r.x = a_if; r.y = a_go;
            red[((qr - 1) * 8 + ul) * 16 + b] = r;
        }
        __syncthreads();
        if (qr == 0) {
#pragma unroll
            for (int q = 0; q < 3; q++) {
                ulonglong2 r = red[(q * 8 + ul) * 16 + b];
                add2(a_if, r.x);
                add2(a_go, r.y);
            }
            float ai, af, ag, ao;
            unpack2(a_if, ai, af);
            unpack2(a_go, ag, ao);
            float ig = sigmoidf_(ai), fg = sigmoidf_(af);
            float gg = tanhf(ag),     og = sigmoidf_(ao);
            c = fg * c + ig * gg;
            float h = og * tanhf(c);

            __stcg(&hbuf[(size_t)(cur ^ 1) * (CB * CD) + (size_t)b * CD + u], h);
            dec[((size_t)(b * CTD + t)) * CD + u] = h;
        }
        grid_sync_dev(gridDim.x);
    }
}

// ---- fused attention: one block per (b, qt) ----
__global__ void __launch_bounds__(128) attn_kernel(
    const int* __restrict__ eseq,
    const float* __restrict__ q, const float* __restrict__ k,
    const float* __restrict__ v, float* __restrict__ ctx)
{
    __shared__ float qs[CD];
    __shared__ float att[CTE];
    __shared__ float red[128];
    const int tid = threadIdx.x;
    const int b = blockIdx.x >> 7, qt = blockIdx.x & 127;
    const size_t qrow = (size_t)(b * CTD + qt) * CD;

    ((float4*)qs)[tid]       = ((const float4*)(q + qrow))[tid];
    ((float4*)qs)[tid + 128] = ((const float4*)(q + qrow))[tid + 128];
    __syncthreads();

    const float4* kr = (const float4*)(k + (size_t)(b * CTE + tid) * CD);
    float s = 0.0f;
#pragma unroll 8
    for (int k4 = 0; k4 < CD / 4; k4++) {
        float4 kv = kr[k4];
        s = fmaf(qs[k4*4+0], kv.x, s); s = fmaf(qs[k4*4+1], kv.y, s);
        s = fmaf(qs[k4*4+2], kv.z, s); s = fmaf(qs[k4*4+3], kv.w, s);
    }
    s *= 0.03125f;
    if (eseq[b * CTE + tid] == 0) s = -1e30f;

    red[tid] = s; __syncthreads();
#pragma unroll
    for (int o = 64; o > 0; o >>= 1) {
        if (tid < o) red[tid] = fmaxf(red[tid], red[tid + o]);
        __syncthreads();
    }
    float mx = red[0]; __syncthreads();
    float e = expf(s - mx);
    red[tid] = e; __syncthreads();
#pragma unroll
    for (int o = 64; o > 0; o >>= 1) {
        if (tid < o) red[tid] += red[tid + o];
        __syncthreads();
    }
    att[tid] = e / red[0];
    __syncthreads();

    float acc[8] = {0,0,0,0,0,0,0,0};
    for (int kt = 0; kt < CTE; kt++) {
        float a = att[kt];
        const float* vr = v + (size_t)(b * CTE + kt) * CD;
#pragma unroll
        for (int j = 0; j < 8; j++) acc[j] = fmaf(a, vr[tid + j * 128], acc[j]);
    }
    float* cr = ctx + (size_t)(b * CTD + qt) * CD;
#pragma unroll
    for (int j = 0; j < 8; j++) cr[tid + j * 128] = acc[j];
}

// ---- tanh(dec + ctx) -> layernorm ----
__global__ void __launch_bounds__(256) tanh_ln_kernel(
    const float* __restrict__ dec, const float* __restrict__ ctx,
    const float* __restrict__ gamma, const float* __restrict__ beta,
    float* __restrict__ ln)
{
    __shared__ float rs[8], rss[8];
    const int tid = threadIdx.x;
    const int row = blockIdx.x;
    const float4 a = ((const float4*)(dec + (size_t)row * CD))[tid];
    const float4 b = ((const float4*)(ctx + (size_t)row * CD))[tid];
    float t0 = tanhf(a.x + b.x), t1 = tanhf(a.y + b.y);
    float t2 = tanhf(a.z + b.z), t3 = tanhf(a.w + b.w);
    float s = t0 + t1 + t2 + t3;
    float ss = t0*t0 + t1*t1 + t2*t2 + t3*t3;
#pragma unroll
    for (int o = 16; o > 0; o >>= 1) {
        s  += __shfl_xor_sync(0xffffffffu, s, o);
        ss += __shfl_xor_sync(0xffffffffu, ss, o);
    }
    if ((tid & 31) == 0) { rs[tid >> 5] = s; rss[tid >> 5] = ss; }
    __syncthreads();
    if (tid < 8) { s = rs[tid]; ss = rss[tid]; }
    else { s = 0; ss = 0; }
    if (tid < 32) {
#pragma unroll
        for (int o = 4; o > 0; o >>= 1) {
            s  += __shfl_xor_sync(0xffffffffu, s, o);
            ss += __shfl_xor_sync(0xffffffffu, ss, o);
        }
        if (tid == 0) { rs[0] = s; rss[0] = ss; }
    }
    __syncthreads();
    float mu = rs[0] * (1.0f / CD);
    float var = rss[0] * (1.0f / CD) - mu * mu;
    float rstd = rsqrtf(var + 1e-5f);
    const float4 g = ((const float4*)gamma)[tid];
    const float4 be = ((const float4*)beta)[tid];
    float4 o;
    o.x = (t0 - mu) * rstd * g.x + be.x;
    o.y = (t1 - mu) * rstd * g.y + be.y;
    o.z = (t2 - mu) * rstd * g.z + be.z;
    o.w = (t3 - mu) * rstd * g.w + be.w;
    ((float4*)(ln + (size_t)row * CD))[tid] = o;
}

extern "C" void kernel_launch(void* const* d_in, const int* in_sizes, int n_in,
                              void* d_out, int out_size) {
    const int*   eseq  = (const int*)d_in[0];
    const int*   dseq  = (const int*)d_in[1];
    const float* eemb  = (const float*)d_in[2];
    const float* demb  = (const float*)d_in[3];
    const float* Wih_f = (const float*)d_in[4];
    const float* Whh_f = (const float*)d_in[5];
    const float* bih_f = (const float*)d_in[6];
    const float* bhh_f = (const float*)d_in[7];
    const float* Wih_b = (const float*)d_in[8];
    const float* Whh_b = (const float*)d_in[9];
    const float* bih_b = (const float*)d_in[10];
    const float* bhh_b = (const float*)d_in[11];
    const float* Wih_d = (const float*)d_in[12];
    const float* Whh_d = (const float*)d_in[13];
    const float* bih_d = (const float*)d_in[14];
    const float* bhh_d = (const float*)d_in[15];
    const float* Wq = (const float*)d_in[16];
    const float* bq = (const float*)d_in[17];
    const float* Wk = (const float*)d_in[18];
    const float* bk = (const float*)d_in[19];
    const float* Wv = (const float*)d_in[20];
    const float* bv = (const float*)d_in[21];
    const float* Wfc = (const float*)d_in[22];
    const float* bfc = (const float*)d_in[23];
    const float* gamma = (const float*)d_in[24];
    const float* beta  = (const float*)d_in[25];
    float* out = (float*)d_out;

    float* S = nullptr;
    cudaGetSymbolAddress((void**)&S, g_scratch);
    float* xe  = S + OFF_XE;
    float* xd  = S + OFF_XD;
    float* xgf = S + OFF_XGF;
    float* xgb = S + OFF_XGB;
    float* xgd = S + OFF_XGD;
    float* enc = S + OFF_ENC;
    float* dec = S + OFF_DEC;
    float* q   = S + OFF_Q;
    float* k   = S + OFF_K;
    float* v   = S + OFF_V;
    float* ctx = S + OFF_CTX;
    float* ln  = S + OFF_LN;
    float* heb = S + OFF_HE;
    float* hdb = S + OFF_HD;
    float* cdi = S + OFF_CDI;

    cudaFuncSetAttribute(enc_rnn_kernel,
                         cudaFuncAttributeMaxDynamicSharedMemorySize, ENC_SMEM);
    cudaFuncSetAttribute(dec_rnn_kernel,
                         cudaFuncAttributeMaxDynamicSharedMemorySize, DEC_SMEM);
    cudaFuncSetAttribute(gemm_tc_kernel,
                         cudaFuncAttributeMaxDynamicSharedMemorySize, GEMM_SMEM);

    const int M = CB * CTE;  // 2048 (== CB*CTD)

    embed_kernel<<<CB * CTE + CB * CTD, 128>>>(eseq, dseq, eemb, demb, xe, xd);

    gemm_tc_kernel<<<dim3(M/BM, 4*CH/BN), 256, GEMM_SMEM>>>(xe, Wih_f, bih_f, bhh_f, xgf, 4*CH, CE);
    gemm_tc_kernel<<<dim3(M/BM, 4*CH/BN), 256, GEMM_SMEM>>>(xe, Wih_b, bih_b, bhh_b, xgb, 4*CH, CE);
    gemm_tc_kernel<<<dim3(M/BM, 4*CD/BN), 256, GEMM_SMEM>>>(xd, Wih_d, bih_d, bhh_d, xgd, 4*CD, CE);

    enc_rnn_kernel<<<128, 512, ENC_SMEM>>>(Whh_f, Whh_b, xgf, xgb, enc, heb, hdb, cdi);
    dec_rnn_kernel<<<128, 512, DEC_SMEM>>>(Whh_d, xgd, dec, hdb, cdi);

    gemm_tc_kernel<<<dim3(M/BM, CD/BN), 256, GEMM_SMEM>>>(dec, Wq, bq, nullptr, q, CD, CD);
    gemm_tc_kernel<<<dim3(M/BM, CD/BN), 256, GEMM_SMEM>>>(enc, Wk, bk, nullptr, k, CD, CD);
    gemm_tc_kernel<<<dim3(M/BM, CD/BN), 256, GEMM_SMEM>>>(enc, Wv, bv, nullptr, v, CD, CD);

    attn_kernel<<<CB * CTD, 128>>>(eseq, q, k, v, ctx);
    tanh_ln_kernel<<<CB * CTD, 256>>>(dec, ctx, gamma, beta, ln);

    gemm_tc_kernel<<<dim3(M/BM, CV/BN), 256, GEMM_SMEM>>>(ln, Wfc, bfc, nullptr, out, CV, CD);
}